// round 13
// baseline (speedup 1.0000x reference)
#include <cuda_runtime.h>
#include <cuda_fp16.h>
#include <math.h>
#include <stdint.h>

// Problem constants
#define BB   4
#define LL   1024
#define DD   768
#define HH   12
#define FF_  3072
#define PP   32
#define MAXD_ 256
#define ML   (BB*LL)   // 4096 rows
#define QKVS 2304      // fused QKV row stride

// ---------------- scratch (device globals; no runtime allocation) ----------
__device__ __half g_qin[ML*DD];
__device__ __half g_QKV[ML*QKVS];
__device__ __half g_Vt[(size_t)BB*HH*64*LL];   // [b][h][d][j]
__device__ __half g_ctx[ML*DD];
__device__ float  g_res1[ML*DD];
__device__ __half g_h2[ML*DD];
__device__ __half g_ff[ML*FF_];
// transposed weights [N,K] fp16
__device__ __half g_WqkvT[QKVS*DD];
__device__ float  g_bqkv[QKVS];
__device__ __half g_WoT[DD*DD];
__device__ __half g_W1T[FF_*DD];
__device__ __half g_W2T[DD*FF_];

// single extern shared symbol for all kernels
extern __shared__ char smem_raw[];

// ======================= helpers =====================
__device__ __forceinline__ uint32_t smem_u32(const void* p) {
    uint32_t a;
    asm("{ .reg .u64 t; cvta.to.shared.u64 t, %1; cvt.u32.u64 %0, t; }" : "=r"(a) : "l"(p));
    return a;
}

#define CP_ASYNC16(dst, src) \
    asm volatile("cp.async.ca.shared.global [%0], [%1], 16;" :: "r"(dst), "l"(src) : "memory")
#define CP_COMMIT()  asm volatile("cp.async.commit_group;" ::: "memory")
#define CP_WAIT1()   asm volatile("cp.async.wait_group 1;" ::: "memory")
#define CP_WAIT0()   asm volatile("cp.async.wait_group 0;" ::: "memory")

__device__ __forceinline__ void mma_f16(float c[4], uint32_t a0, uint32_t a1,
                                        uint32_t a2, uint32_t a3,
                                        uint32_t b0, uint32_t b1) {
    asm volatile(
        "mma.sync.aligned.m16n8k16.row.col.f32.f16.f16.f32 "
        "{%0,%1,%2,%3}, {%4,%5,%6,%7}, {%8,%9}, {%0,%1,%2,%3};"
        : "+f"(c[0]), "+f"(c[1]), "+f"(c[2]), "+f"(c[3])
        : "r"(a0), "r"(a1), "r"(a2), "r"(a3), "r"(b0), "r"(b1));
}
__device__ __forceinline__ void ldsm4(uint32_t r[4], uint32_t addr) {
    asm volatile("ldmatrix.sync.aligned.m8n8.x4.shared.b16 {%0,%1,%2,%3}, [%4];"
                 : "=r"(r[0]), "=r"(r[1]), "=r"(r[2]), "=r"(r[3]) : "r"(addr));
}
__device__ __forceinline__ uint32_t h2u(__half2 h) { return *(uint32_t*)&h; }

// pack two floats into half2 (lo, hi) and apply ex2 elementwise
__device__ __forceinline__ uint32_t pack_ex2_h2(float hi, float lo) {
    uint32_t d;
    asm("cvt.rn.f16x2.f32 %0, %1, %2;" : "=r"(d) : "f"(hi), "f"(lo));
    asm("ex2.approx.f16x2 %0, %0;" : "+r"(d));
    return d;
}

// ---------------- all weight transposes in ONE launch (fp16 out) -----------
// blocks: [0,1728) Wq/Wk/Wv -> WqkvT, [1728,2304) Wo, [2304,4608) W1, [4608,6912) W2
__global__ void transpose_all(const float* __restrict__ Wq, const float* __restrict__ Wk,
                              const float* __restrict__ Wv, const float* __restrict__ Wo,
                              const float* __restrict__ W1, const float* __restrict__ W2,
                              const float* __restrict__ bq, const float* __restrict__ bk,
                              const float* __restrict__ bv,
                              __half* __restrict__ WqkvT, float* __restrict__ bqkv,
                              __half* __restrict__ WoT, __half* __restrict__ W1T,
                              __half* __restrict__ W2T) {
    __shared__ float t[32][33];
    int idx = blockIdx.x;
    const float* src; __half* dst; int R, C, bx, by; size_t dstoff = 0;
    if (idx < 1728) {
        int z = idx / 576, lo = idx % 576;
        src = (z == 0) ? Wq : (z == 1) ? Wk : Wv;
        dst = WqkvT; R = DD; C = DD; bx = lo % 24; by = lo / 24;
        dstoff = (size_t)z * DD * DD;
    } else if (idx < 2304) {
        int lo = idx - 1728; src = Wo; dst = WoT; R = DD; C = DD; bx = lo % 24; by = lo / 24;
    } else if (idx < 4608) {
        int lo = idx - 2304; src = W1; dst = W1T; R = DD; C = FF_; bx = lo % 96; by = lo / 96;
    } else {
        int lo = idx - 4608; src = W2; dst = W2T; R = FF_; C = DD; bx = lo % 24; by = lo / 24;
    }
    int c0 = bx * 32, r0 = by * 32;
    int x = threadIdx.x, y = threadIdx.y;
    #pragma unroll
    for (int i = 0; i < 32; i += 8)
        t[y + i][x] = src[(size_t)(r0 + y + i) * C + c0 + x];
    __syncthreads();
    #pragma unroll
    for (int i = 0; i < 32; i += 8)
        dst[dstoff + (size_t)(c0 + y + i) * R + r0 + x] = __float2half(t[x][y + i]);
    if (idx == 0) {
        int tid = y * 32 + x;
        for (int i = tid; i < QKVS; i += 256)
            bqkv[i] = (i < 768) ? bq[i] : (i < 1536) ? bk[i - 768] : bv[i - 1536];
    }
}

// ---------------- LayerNorm (fp16 output) ----------------
__global__ void ln_kernel(const float* __restrict__ x, const float* __restrict__ g,
                          const float* __restrict__ b, __half* __restrict__ y, float eps) {
    int row = blockIdx.x;
    const float* xr = x + (size_t)row * DD;
    __shared__ float red[256];
    int tid = threadIdx.x;

    float s = 0.f;
    for (int d = tid; d < DD; d += 256) s += xr[d];
    red[tid] = s; __syncthreads();
    #pragma unroll
    for (int o = 128; o > 0; o >>= 1) { if (tid < o) red[tid] += red[tid + o]; __syncthreads(); }
    float mu = red[0] * (1.f / DD);
    __syncthreads();

    float v = 0.f;
    for (int d = tid; d < DD; d += 256) { float t = xr[d] - mu; v += t * t; }
    red[tid] = v; __syncthreads();
    #pragma unroll
    for (int o = 128; o > 0; o >>= 1) { if (tid < o) red[tid] += red[tid + o]; __syncthreads(); }
    float inv = rsqrtf(red[0] * (1.f / DD) + eps);

    __half* yr = y + (size_t)row * DD;
    for (int d = tid; d < DD; d += 256)
        yr[d] = __float2half((xr[d] - mu) * inv * g[d] + b[d]);
}

// ====== fp16 mma GEMM, 64x64 warp tiles (unchanged from R12) ===============
#define NSTAGE 3
#define GSMEM (NSTAGE * 32768)   // 96KB

template<int EPI, int HALFOUT, int VTOUT>
__global__ __launch_bounds__(128, 2) void mma_gemm(
    const __half* __restrict__ A, const __half* __restrict__ Bt,
    const float* __restrict__ bias, const float* __restrict__ res,
    void* __restrict__ Cv, __half* __restrict__ Vtp, int K, int N) {
    uint32_t smem_base = smem_u32(smem_raw);

    int tid = threadIdx.x;
    int wid = tid >> 5, lane = tid & 31;
    int r = lane >> 2, l = lane & 3;
    int quad = lane >> 3, qr = lane & 7;
    int row0 = blockIdx.y * 128, col0 = blockIdx.x * 128;
    int m0 = (wid & 1) * 64, n0 = (wid >> 1) * 64;

    int m_l = tid >> 3, s_l = tid & 7;
    const __half* srcA = A + (size_t)(row0 + m_l) * K + s_l * 8;
    const __half* srcB = Bt + (size_t)(col0 + m_l) * K + s_l * 8;
    uint32_t dA0 = smem_base + m_l * 128 + ((s_l ^ (m_l & 7)) << 4);
    uint32_t dB0 = dA0 + 16384;

    int arow = m0 + ((quad & 1) << 3) + qr;
    int xA = arow & 7, qhA = quad >> 1;
    uint32_t baseA = smem_base + arow * 128;
    int brow = n0 + ((quad >> 1) << 3) + qr;
    int xB = brow & 7, qhB = quad & 1;
    uint32_t baseB = smem_base + 16384 + brow * 128;

    int nc = K >> 6;

    float acc[4][8][4];
    #pragma unroll
    for (int i = 0; i < 4; i++)
        #pragma unroll
        for (int j = 0; j < 8; j++)
            #pragma unroll
            for (int k = 0; k < 4; k++) acc[i][j][k] = 0.f;

    #pragma unroll
    for (int s = 0; s < NSTAGE - 1; s++) {
        uint32_t so = s * 32768;
        #pragma unroll
        for (int u = 0; u < 8; u++) {
            CP_ASYNC16(dA0 + so + u * 2048, srcA + (size_t)(s * 64) + (size_t)u * 16 * K);
            CP_ASYNC16(dB0 + so + u * 2048, srcB + (size_t)(s * 64) + (size_t)u * 16 * K);
        }
        CP_COMMIT();
    }

    for (int c = 0; c < nc; c++) {
        CP_WAIT1();
        __syncthreads();
        int nstg = c + NSTAGE - 1;
        if (nstg < nc) {
            uint32_t so = (nstg % NSTAGE) * 32768;
            #pragma unroll
            for (int u = 0; u < 8; u++) {
                CP_ASYNC16(dA0 + so + u * 2048, srcA + (size_t)(nstg * 64) + (size_t)u * 16 * K);
                CP_ASYNC16(dB0 + so + u * 2048, srcB + (size_t)(nstg * 64) + (size_t)u * 16 * K);
            }
        }
        CP_COMMIT();

        uint32_t so = (c % NSTAGE) * 32768;
        #pragma unroll
        for (int ks = 0; ks < 4; ks++) {
            uint32_t segA = ((2 * ks + qhA) ^ xA) << 4;
            uint32_t segB = ((2 * ks + qhB) ^ xB) << 4;
            uint32_t a[4][4];
            #pragma unroll
            for (int mi = 0; mi < 4; mi++)
                ldsm4(a[mi], baseA + so + mi * 2048 + segA);
            #pragma unroll
            for (int p = 0; p < 4; p++) {
                uint32_t br[4];
                ldsm4(br, baseB + so + p * 2048 + segB);
                #pragma unroll
                for (int mi = 0; mi < 4; mi++) {
                    mma_f16(acc[mi][2 * p + 0], a[mi][0], a[mi][1], a[mi][2], a[mi][3], br[0], br[1]);
                    mma_f16(acc[mi][2 * p + 1], a[mi][0], a[mi][1], a[mi][2], a[mi][3], br[2], br[3]);
                }
            }
        }
    }

    bool vtile = VTOUT && (col0 >= 1536);
    #pragma unroll
    for (int mi = 0; mi < 4; mi++) {
        int rr = row0 + m0 + 16 * mi + r;
        #pragma unroll
        for (int nj = 0; nj < 8; nj++) {
            int cc = col0 + n0 + 8 * nj + 2 * l;
            float b0 = bias[cc], b1 = bias[cc + 1];
            float v0 = acc[mi][nj][0] + b0;
            float v1 = acc[mi][nj][1] + b1;
            float v2 = acc[mi][nj][2] + b0;
            float v3 = acc[mi][nj][3] + b1;
            if (EPI == 1) {
                const float* rp0 = res + (size_t)rr * N + cc;
                const float* rp1 = res + (size_t)(rr + 8) * N + cc;
                v0 += rp0[0]; v1 += rp0[1];
                v2 += rp1[0]; v3 += rp1[1];
            }
            if (EPI == 2) {
                v0 = 0.5f * v0 * (1.f + erff(v0 * 0.70710678118654752f));
                v1 = 0.5f * v1 * (1.f + erff(v1 * 0.70710678118654752f));
                v2 = 0.5f * v2 * (1.f + erff(v2 * 0.70710678118654752f));
                v3 = 0.5f * v3 * (1.f + erff(v3 * 0.70710678118654752f));
            }
            if (VTOUT) {
                if (vtile) {
                    int d = cc - 1536;
                    int hh = d >> 6, dl = d & 63;
                    int b = rr >> 10, j = rr & 1023;
                    __half* vp = Vtp + ((size_t)(b * HH + hh) * 64 + dl) * LL + j;
                    vp[0] = __float2half(v0);
                    vp[LL] = __float2half(v1);
                    vp[8] = __float2half(v2);
                    vp[LL + 8] = __float2half(v3);
                    continue;
                }
            }
            if (HALFOUT) {
                __half* Ch = (__half*)Cv;
                *(__half2*)(Ch + (size_t)rr * N + cc) = __floats2half2_rn(v0, v1);
                *(__half2*)(Ch + (size_t)(rr + 8) * N + cc) = __floats2half2_rn(v2, v3);
            } else {
                float* Cf = (float*)Cv;
                float2 o01 = { v0, v1 };
                float2 o23 = { v2, v3 };
                *(float2*)(Cf + (size_t)rr * N + cc) = o01;
                *(float2*)(Cf + (size_t)(rr + 8) * N + cc) = o23;
            }
        }
    }
}

// ================= fp16 flash attention, register-resident P ===============
// smem: Q 16KB | K0 8KB | K1 8KB | V0 8KB | V1 8KB | tables
#define ATB_QS 0
#define ATB_K0 16384
#define ATB_K1 24576
#define ATB_V0 32768
#define ATB_V1 40960
#define ATB_TB 49152
#define TB_REL  0
#define TB_PT   513
#define TB_LEX  1537    // [2][64]
#define TB_PIDQ 1665    // int [128]
#define TB_PIDK 1793    // int [2][64]
#define TB_END  1921
#define ATTN_SMEM (ATB_TB + TB_END * 4)

__global__ __launch_bounds__(256, 2) void attn_mma(
    const __half* __restrict__ QKV, const __half* __restrict__ Vt,
    const float* __restrict__ rel_emb, const float* __restrict__ ptab,
    const int* __restrict__ pids, const float* __restrict__ lex,
    __half* __restrict__ ctx) {
    char* sb = smem_raw;
    float* tb = (float*)(sb + ATB_TB);
    int* tbi = (int*)tb;
    uint32_t sbase = smem_u32(sb);
    const float LOG2E = 1.44269504089f;

    int tid = threadIdx.x;
    int w = tid >> 5, lane = tid & 31;
    int r = lane >> 2, l = lane & 3;
    int quad = lane >> 3, qr = lane & 7;
    int h = blockIdx.y, bbx = blockIdx.z;
    int i0 = blockIdx.x * 128;

    for (int i = tid; i < 513; i += 256) tb[TB_REL + i] = rel_emb[i * HH + h];
    for (int i = tid; i < 1024; i += 256) tb[TB_PT + i] = ptab[i * HH + h];
    if (tid < 128) tbi[TB_PIDQ + tid] = pids[bbx * LL + i0 + tid];
    // Q tile: scale by 1/8, store swizzled
    {
        __half2 sc = __float2half2_rn(0.125f);
        #pragma unroll
        for (int u = 0; u < 4; u++) {
            int idx = u * 256 + tid;
            int row = idx >> 3, seg = idx & 7;
            const __half2* src = (const __half2*)(QKV + (size_t)(bbx * LL + i0 + row) * QKVS + h * 64 + seg * 8);
            __half2 v0 = __hmul2(src[0], sc), v1 = __hmul2(src[1], sc);
            __half2 v2 = __hmul2(src[2], sc), v3 = __hmul2(src[3], sc);
            uint4 pk = { h2u(v0), h2u(v1), h2u(v2), h2u(v3) };
            *(uint4*)(sb + ATB_QS + row * 128 + ((seg ^ (row & 7)) << 4)) = pk;
        }
    }
    // prologue: tile 0 K/V + pid/lex slot 0
    if (tid < 64) {
        tbi[TB_PIDK + tid] = pids[bbx * LL + tid];
        tb[TB_LEX + tid] = lex[bbx * LL + tid];
    }
    {
        #pragma unroll
        for (int u = 0; u < 2; u++) {
            int idx = u * 256 + tid;
            int row = idx >> 3, seg = idx & 7;
            uint32_t sw = row * 128 + ((seg ^ (row & 7)) << 4);
            CP_ASYNC16(sbase + ATB_K0 + sw,
                       QKV + (size_t)(bbx * LL + row) * QKVS + 768 + h * 64 + seg * 8);
            CP_ASYNC16(sbase + ATB_V0 + sw,
                       Vt + ((size_t)(bbx * HH + h) * 64 + row) * LL + seg * 8);
        }
        CP_COMMIT();
    }
    __syncthreads();

    // Q A-frags resident
    uint32_t aq[4][4];
    {
        int rowA = w * 16 + ((quad & 1) << 3) + qr;
        int xA = rowA & 7, qh = quad >> 1;
        uint32_t baseA = sbase + ATB_QS + rowA * 128;
        #pragma unroll
        for (int ks = 0; ks < 4; ks++)
            ldsm4(aq[ks], baseA + (((2 * ks + qh) ^ xA) << 4));
    }
    int pq0 = tbi[TB_PIDQ + w * 16 + r] * PP;
    int pq1 = tbi[TB_PIDQ + w * 16 + r + 8] * PP;

    float o[8][4];
    #pragma unroll
    for (int nj = 0; nj < 8; nj++)
        #pragma unroll
        for (int k = 0; k < 4; k++) o[nj][k] = 0.f;

    // B-frag row pattern for K and V (rows = j or d, + p*16)
    int rowK = ((quad >> 1) << 3) + qr;
    int xK = rowK & 7, qhK = quad & 1;
    uint32_t baseK[2] = { sbase + ATB_K0 + rowK * 128, sbase + ATB_K1 + rowK * 128 };
    uint32_t baseV[2] = { sbase + ATB_V0 + rowK * 128, sbase + ATB_V1 + rowK * 128 };

    // softmax state in registers (identical across the 4 lanes of each group)
    float m0v = -1e30f, m1v = -1e30f, ls0 = 0.f, ls1 = 0.f;

    for (int t = 0; t < 16; t++) {
        CP_WAIT0();
        __syncthreads();
        int cur = t & 1;
        // prefetch next tile
        if (t + 1 < 16) {
            int j1 = (t + 1) * 64;
            int nsl = (t + 1) & 1;
            if (tid < 64) {
                tbi[TB_PIDK + nsl * 64 + tid] = pids[bbx * LL + j1 + tid];
                tb[TB_LEX + nsl * 64 + tid] = lex[bbx * LL + j1 + tid];
            }
            uint32_t kOff = nsl ? ATB_K1 : ATB_K0;
            uint32_t vOff = nsl ? ATB_V1 : ATB_V0;
            #pragma unroll
            for (int u = 0; u < 2; u++) {
                int idx = u * 256 + tid;
                int row = idx >> 3, seg = idx & 7;
                uint32_t sw = row * 128 + ((seg ^ (row & 7)) << 4);
                CP_ASYNC16(sbase + kOff + sw,
                           QKV + (size_t)(bbx * LL + j1 + row) * QKVS + 768 + h * 64 + seg * 8);
                CP_ASYNC16(sbase + vOff + sw,
                           Vt + ((size_t)(bbx * HH + h) * 64 + row) * LL + j1 + seg * 8);
            }
            CP_COMMIT();
        }

        int j0 = t * 64;
        // S = Q @ K^T
        float s[8][4];
        #pragma unroll
        for (int nj = 0; nj < 8; nj++)
            #pragma unroll
            for (int k = 0; k < 4; k++) s[nj][k] = 0.f;
        #pragma unroll
        for (int ks = 0; ks < 4; ks++) {
            #pragma unroll
            for (int p = 0; p < 4; p++) {
                uint32_t br[4];
                ldsm4(br, baseK[cur] + p * 2048 + (((2 * ks + qhK) ^ xK) << 4));
                mma_f16(s[2 * p + 0], aq[ks][0], aq[ks][1], aq[ks][2], aq[ks][3], br[0], br[1]);
                mma_f16(s[2 * p + 1], aq[ks][0], aq[ks][1], aq[ks][2], aq[ks][3], br[2], br[3]);
            }
        }

        // biases + row max
        const float* lexS = tb + TB_LEX + cur * 64;
        const int* pidkS = tbi + TB_PIDK + cur * 64;
        int rg0 = i0 + w * 16 + r, rg1 = rg0 + 8;
        float mx0 = -1e30f, mx1 = -1e30f;
        #pragma unroll
        for (int nj = 0; nj < 8; nj++) {
            int ca = nj * 8 + 2 * l;
            int jga = j0 + ca;
            int pka = pidkS[ca], pkb = pidkS[ca + 1];
            float lxa = lexS[ca], lxb = lexS[ca + 1];
            int ra0 = min(max(jga - rg0, -MAXD_), MAXD_) + MAXD_;
            int rb0 = min(max(jga + 1 - rg0, -MAXD_), MAXD_) + MAXD_;
            int ra1 = min(max(jga - rg1, -MAXD_), MAXD_) + MAXD_;
            int rb1 = min(max(jga + 1 - rg1, -MAXD_), MAXD_) + MAXD_;
            s[nj][0] += tb[TB_REL + ra0] + tb[TB_PT + pq0 + pka] + lxa;
            s[nj][1] += tb[TB_REL + rb0] + tb[TB_PT + pq0 + pkb] + lxb;
            s[nj][2] += tb[TB_REL + ra1] + tb[TB_PT + pq1 + pka] + lxa;
            s[nj][3] += tb[TB_REL + rb1] + tb[TB_PT + pq1 + pkb] + lxb;
            mx0 = fmaxf(mx0, fmaxf(s[nj][0], s[nj][1]));
            mx1 = fmaxf(mx1, fmaxf(s[nj][2], s[nj][3]));
        }
        mx0 = fmaxf(mx0, __shfl_xor_sync(0xffffffffu, mx0, 1));
        mx0 = fmaxf(mx0, __shfl_xor_sync(0xffffffffu, mx0, 2));
        mx1 = fmaxf(mx1, __shfl_xor_sync(0xffffffffu, mx1, 1));
        mx1 = fmaxf(mx1, __shfl_xor_sync(0xffffffffu, mx1, 2));

        float mn0 = fmaxf(m0v, mx0), mn1 = fmaxf(m1v, mx1);
        float al0 = exp2f((m0v - mn0) * LOG2E), al1 = exp2f((m1v - mn1) * LOG2E);
        m0v = mn0; m1v = mn1;

        // exp via ex2.f16x2 -> packed half2 = PV A-fragments directly
        uint32_t ph0[8], ph1[8];
        float sum0 = 0.f, sum1 = 0.f;
        #pragma unroll
        for (int nj = 0; nj < 8; nj++) {
            float t0 = (s[nj][0] - mn0) * LOG2E;
            float t1 = (s[nj][1] - mn0) * LOG2E;
            float t2 = (s[nj][2] - mn1) * LOG2E;
            float t3 = (s[nj][3] - mn1) * LOG2E;
            ph0[nj] = pack_ex2_h2(t1, t0);   // lo = t0 (col 2l), hi = t1 (col 2l+1)
            ph1[nj] = pack_ex2_h2(t3, t2);
            float2 f0 = __half22float2(*(__half2*)&ph0[nj]);
            float2 f1 = __half22float2(*(__half2*)&ph1[nj]);
            sum0 += f0.x + f0.y;
            sum1 += f1.x + f1.y;
            o[nj][0] *= al0; o[nj][1] *= al0; o[nj][2] *= al1; o[nj][3] *= al1;
        }
        sum0 += __shfl_xor_sync(0xffffffffu, sum0, 1);
        sum0 += __shfl_xor_sync(0xffffffffu, sum0, 2);
        sum1 += __shfl_xor_sync(0xffffffffu, sum1, 1);
        sum1 += __shfl_xor_sync(0xffffffffu, sum1, 2);
        ls0 = ls0 * al0 + sum0;
        ls1 = ls1 * al1 + sum1;

        // O += P @ V (P fragments straight from registers)
        #pragma unroll
        for (int kg = 0; kg < 4; kg++) {
            uint32_t a0 = ph0[2 * kg], a1 = ph1[2 * kg];
            uint32_t a2 = ph0[2 * kg + 1], a3 = ph1[2 * kg + 1];
            #pragma unroll
            for (int p = 0; p < 4; p++) {
                uint32_t bv[4];
                ldsm4(bv, baseV[cur] + p * 2048 + (((2 * kg + qhK) ^ xK) << 4));
                mma_f16(o[2 * p + 0], a0, a1, a2, a3, bv[0], bv[1]);
                mma_f16(o[2 * p + 1], a0, a1, a2, a3, bv[2], bv[3]);
            }
        }
    }

    // finalize
    float inv0 = 1.f / ls0;
    float inv1 = 1.f / ls1;
    int row0g = bbx * LL + i0 + w * 16 + r;
    #pragma unroll
    for (int nj = 0; nj < 8; nj++) {
        *(__half2*)(ctx + (size_t)row0g * DD + h * 64 + nj * 8 + 2 * l)
            = __floats2half2_rn(o[nj][0] * inv0, o[nj][1] * inv0);
        *(__half2*)(ctx + (size_t)(row0g + 8) * DD + h * 64 + nj * 8 + 2 * l)
            = __floats2half2_rn(o[nj][2] * inv1, o[nj][3] * inv1);
    }
}

// ---------------- launch ----------------
extern "C" void kernel_launch(void* const* d_in, const int* in_sizes, int n_in,
                              void* d_out, int out_size) {
    const float* x      = (const float*)d_in[0];
    const int*   postag = (const int*)  d_in[1];
    const float* lexm   = (const float*)d_in[2];
    const float* ln1g   = (const float*)d_in[3];
    const float* ln1b   = (const float*)d_in[4];
    const float* Wq     = (const float*)d_in[5];
    const float* bq     = (const float*)d_in[6];
    const float* Wk     = (const float*)d_in[7];
    const float* bk     = (const float*)d_in[8];
    const float* Wv     = (const float*)d_in[9];
    const float* bv     = (const float*)d_in[10];
    const float* Wo     = (const float*)d_in[11];
    const float* bo     = (const float*)d_in[12];
    const float* rel    = (const float*)d_in[13];
    const float* ptab   = (const float*)d_in[14];
    const float* ln2g   = (const float*)d_in[15];
    const float* ln2b   = (const float*)d_in[16];
    const float* W1     = (const float*)d_in[17];
    const float* b1     = (const float*)d_in[18];
    const float* W2     = (const float*)d_in[19];
    const float* b2     = (const float*)d_in[20];
    float* out = (float*)d_out;

    __half *qin, *QKVb, *Vt, *ctx, *h2, *ff;
    __half *WqkvT, *WoT, *W1T, *W2T;
    float *res1, *bqkv;
    cudaGetSymbolAddress((void**)&qin,   g_qin);
    cudaGetSymbolAddress((void**)&QKVb,  g_QKV);
    cudaGetSymbolAddress((void**)&Vt,    g_Vt);
    cudaGetSymbolAddress((void**)&ctx,   g_ctx);
    cudaGetSymbolAddress((void**)&res1,  g_res1);
    cudaGetSymbolAddress((void**)&h2,    g_h2);
    cudaGetSymbolAddress((void**)&ff,    g_ff);
    cudaGetSymbolAddress((void**)&WqkvT, g_WqkvT);
    cudaGetSymbolAddress((void**)&bqkv,  g_bqkv);
    cudaGetSymbolAddress((void**)&WoT,   g_WoT);
    cudaGetSymbolAddress((void**)&W1T,   g_W1T);
    cudaGetSymbolAddress((void**)&W2T,   g_W2T);

    cudaFuncSetAttribute(attn_mma, cudaFuncAttributeMaxDynamicSharedMemorySize, ATTN_SMEM);
    cudaFuncSetAttribute(mma_gemm<0,1,1>, cudaFuncAttributeMaxDynamicSharedMemorySize, GSMEM);
    cudaFuncSetAttribute(mma_gemm<1,0,0>, cudaFuncAttributeMaxDynamicSharedMemorySize, GSMEM);
    cudaFuncSetAttribute(mma_gemm<2,1,0>, cudaFuncAttributeMaxDynamicSharedMemorySize, GSMEM);

    // 0: all weight transposes
    transpose_all<<<6912, dim3(32, 8)>>>(Wq, Wk, Wv, Wo, W1, W2, bq, bk, bv,
                                         WqkvT, bqkv, WoT, W1T, W2T);
    // 1: LN1 -> fp16
    ln_kernel<<<ML, 256>>>(x, ln1g, ln1b, qin, 1e-6f);
    // 2: fused QKV projection (V written transposed to Vt)
    mma_gemm<0,1,1><<<dim3(QKVS / 128, ML / 128), 128, GSMEM>>>(qin, WqkvT, bqkv, nullptr, QKVb, Vt, DD, QKVS);
    // 3: attention   <- ncu capture
    attn_mma<<<dim3(LL / 128, HH, BB), 256, ATTN_SMEM>>>(QKVb, Vt, rel, ptab, postag, lexm, ctx);
    // 4: output projection + residual
    mma_gemm<1,0,0><<<dim3(DD / 128, ML / 128), 128, GSMEM>>>(ctx, WoT, bo, x, res1, nullptr, DD, DD);
    // 5: LN2 -> fp16
    ln_kernel<<<ML, 256>>>(res1, ln2g, ln2b, h2, 1e-5f);
    // 6: FFN up + GELU
    mma_gemm<2,1,0><<<dim3(FF_ / 128, ML / 128), 128, GSMEM>>>(h2, W1T, b1, nullptr, ff, nullptr, DD, FF_);
    // 7: FFN down + bias + residual -> out
    mma_gemm<1,0,0><<<dim3(DD / 128, ML / 128), 128, GSMEM>>>(ff, W2T, b2, res1, out, nullptr, FF_, DD);
}

// round 15
// speedup vs baseline: 1.5326x; 1.5326x over previous
#include <cuda_runtime.h>
#include <cuda_fp16.h>
#include <math.h>
#include <stdint.h>

// Problem constants
#define BB   4
#define LL   1024
#define DD   768
#define HH   12
#define FF_  3072
#define PP   32
#define MAXD_ 256
#define ML   (BB*LL)   // 4096 rows
#define QKVS 2304      // fused QKV row stride

// ---------------- scratch (device globals; no runtime allocation) ----------
__device__ __half g_qin[ML*DD];
__device__ __half g_QKV[ML*QKVS];
__device__ __half g_Vt[(size_t)BB*HH*64*LL];   // [b][h][d][j]
__device__ __half g_ctx[ML*DD];
__device__ float  g_res1[ML*DD];
__device__ __half g_h2[ML*DD];
__device__ __half g_ff[ML*FF_];
// transposed weights [N,K] fp16
__device__ __half g_WqkvT[QKVS*DD];
__device__ float  g_bqkv[QKVS];
__device__ __half g_WoT[DD*DD];
__device__ __half g_W1T[FF_*DD];
__device__ __half g_W2T[DD*FF_];

// single extern shared symbol for all kernels
extern __shared__ char smem_raw[];

// ======================= helpers =====================
__device__ __forceinline__ uint32_t smem_u32(const void* p) {
    uint32_t a;
    asm("{ .reg .u64 t; cvta.to.shared.u64 t, %1; cvt.u32.u64 %0, t; }" : "=r"(a) : "l"(p));
    return a;
}

#define CP_ASYNC16(dst, src) \
    asm volatile("cp.async.ca.shared.global [%0], [%1], 16;" :: "r"(dst), "l"(src) : "memory")
#define CP_COMMIT()  asm volatile("cp.async.commit_group;" ::: "memory")
#define CP_WAIT1()   asm volatile("cp.async.wait_group 1;" ::: "memory")
#define CP_WAIT0()   asm volatile("cp.async.wait_group 0;" ::: "memory")

__device__ __forceinline__ void mma_f16(float c[4], uint32_t a0, uint32_t a1,
                                        uint32_t a2, uint32_t a3,
                                        uint32_t b0, uint32_t b1) {
    asm volatile(
        "mma.sync.aligned.m16n8k16.row.col.f32.f16.f16.f32 "
        "{%0,%1,%2,%3}, {%4,%5,%6,%7}, {%8,%9}, {%0,%1,%2,%3};"
        : "+f"(c[0]), "+f"(c[1]), "+f"(c[2]), "+f"(c[3])
        : "r"(a0), "r"(a1), "r"(a2), "r"(a3), "r"(b0), "r"(b1));
}
__device__ __forceinline__ void ldsm4(uint32_t r[4], uint32_t addr) {
    asm volatile("ldmatrix.sync.aligned.m8n8.x4.shared.b16 {%0,%1,%2,%3}, [%4];"
                 : "=r"(r[0]), "=r"(r[1]), "=r"(r[2]), "=r"(r[3]) : "r"(addr));
}
__device__ __forceinline__ uint32_t h2u(__half2 h) { return *(uint32_t*)&h; }

// pack two floats into half2 (lo, hi) and apply ex2 elementwise
__device__ __forceinline__ uint32_t pack_ex2_h2(float hi, float lo) {
    uint32_t d;
    asm("cvt.rn.f16x2.f32 %0, %1, %2;" : "=r"(d) : "f"(hi), "f"(lo));
    asm("ex2.approx.f16x2 %0, %0;" : "+r"(d));
    return d;
}

// ---------------- transpose kernels (fp16 out) -----------------------------
__global__ void transpose_wqkv(const float* __restrict__ Wq, const float* __restrict__ Wk,
                               const float* __restrict__ Wv, const float* __restrict__ bq,
                               const float* __restrict__ bk, const float* __restrict__ bv,
                               __half* __restrict__ WqkvT, float* __restrict__ bqkv) {
    __shared__ float t[32][33];
    int idx = blockIdx.x;
    int z = idx / 576, lo = idx % 576;
    const float* src = (z == 0) ? Wq : (z == 1) ? Wk : Wv;
    size_t dstoff = (size_t)z * DD * DD;
    int bx = lo % 24, by = lo / 24;
    int c0 = bx * 32, r0 = by * 32;
    int x = threadIdx.x, y = threadIdx.y;
    #pragma unroll
    for (int i = 0; i < 32; i += 8)
        t[y + i][x] = src[(size_t)(r0 + y + i) * DD + c0 + x];
    __syncthreads();
    #pragma unroll
    for (int i = 0; i < 32; i += 8)
        WqkvT[dstoff + (size_t)(c0 + y + i) * DD + r0 + x] = __float2half(t[x][y + i]);
    if (idx == 0) {
        int tid = y * 32 + x;
        for (int i = tid; i < QKVS; i += 256)
            bqkv[i] = (i < 768) ? bq[i] : (i < 1536) ? bk[i - 768] : bv[i - 1536];
    }
}

__global__ void transpose_wrest(const float* __restrict__ Wo, const float* __restrict__ W1,
                                const float* __restrict__ W2,
                                __half* __restrict__ WoT, __half* __restrict__ W1T,
                                __half* __restrict__ W2T) {
    __shared__ float t[32][33];
    int idx = blockIdx.x;
    const float* src; __half* dst; int R, C, bx, by;
    if (idx < 576) {
        src = Wo; dst = WoT; R = DD; C = DD; bx = idx % 24; by = idx / 24;
    } else if (idx < 2880) {
        int lo = idx - 576; src = W1; dst = W1T; R = DD; C = FF_; bx = lo % 96; by = lo / 96;
    } else {
        int lo = idx - 2880; src = W2; dst = W2T; R = FF_; C = DD; bx = lo % 24; by = lo / 24;
    }
    int c0 = bx * 32, r0 = by * 32;
    int x = threadIdx.x, y = threadIdx.y;
    #pragma unroll
    for (int i = 0; i < 32; i += 8)
        t[y + i][x] = src[(size_t)(r0 + y + i) * C + c0 + x];
    __syncthreads();
    #pragma unroll
    for (int i = 0; i < 32; i += 8)
        dst[(size_t)(c0 + y + i) * R + r0 + x] = __float2half(t[x][y + i]);
}

// ---------------- LayerNorm (fp16 output) ----------------
__global__ void ln_kernel(const float* __restrict__ x, const float* __restrict__ g,
                          const float* __restrict__ b, __half* __restrict__ y, float eps) {
    int row = blockIdx.x;
    const float* xr = x + (size_t)row * DD;
    __shared__ float red[256];
    int tid = threadIdx.x;

    float s = 0.f;
    for (int d = tid; d < DD; d += 256) s += xr[d];
    red[tid] = s; __syncthreads();
    #pragma unroll
    for (int o = 128; o > 0; o >>= 1) { if (tid < o) red[tid] += red[tid + o]; __syncthreads(); }
    float mu = red[0] * (1.f / DD);
    __syncthreads();

    float v = 0.f;
    for (int d = tid; d < DD; d += 256) { float t = xr[d] - mu; v += t * t; }
    red[tid] = v; __syncthreads();
    #pragma unroll
    for (int o = 128; o > 0; o >>= 1) { if (tid < o) red[tid] += red[tid + o]; __syncthreads(); }
    float inv = rsqrtf(red[0] * (1.f / DD) + eps);

    __half* yr = y + (size_t)row * DD;
    for (int d = tid; d < DD; d += 256)
        yr[d] = __float2half((xr[d] - mu) * inv * g[d] + b[d]);
}

// ====== fp16 mma GEMM, 64x64 warp tiles (unchanged from R12) ===============
#define NSTAGE 3
#define GSMEM (NSTAGE * 32768)   // 96KB

template<int EPI, int HALFOUT, int VTOUT>
__global__ __launch_bounds__(128, 2) void mma_gemm(
    const __half* __restrict__ A, const __half* __restrict__ Bt,
    const float* __restrict__ bias, const float* __restrict__ res,
    void* __restrict__ Cv, __half* __restrict__ Vtp, int K, int N) {
    uint32_t smem_base = smem_u32(smem_raw);

    int tid = threadIdx.x;
    int wid = tid >> 5, lane = tid & 31;
    int r = lane >> 2, l = lane & 3;
    int quad = lane >> 3, qr = lane & 7;
    int row0 = blockIdx.y * 128, col0 = blockIdx.x * 128;
    int m0 = (wid & 1) * 64, n0 = (wid >> 1) * 64;

    int m_l = tid >> 3, s_l = tid & 7;
    const __half* srcA = A + (size_t)(row0 + m_l) * K + s_l * 8;
    const __half* srcB = Bt + (size_t)(col0 + m_l) * K + s_l * 8;
    uint32_t dA0 = smem_base + m_l * 128 + ((s_l ^ (m_l & 7)) << 4);
    uint32_t dB0 = dA0 + 16384;

    int arow = m0 + ((quad & 1) << 3) + qr;
    int xA = arow & 7, qhA = quad >> 1;
    uint32_t baseA = smem_base + arow * 128;
    int brow = n0 + ((quad >> 1) << 3) + qr;
    int xB = brow & 7, qhB = quad & 1;
    uint32_t baseB = smem_base + 16384 + brow * 128;

    int nc = K >> 6;

    float acc[4][8][4];
    #pragma unroll
    for (int i = 0; i < 4; i++)
        #pragma unroll
        for (int j = 0; j < 8; j++)
            #pragma unroll
            for (int k = 0; k < 4; k++) acc[i][j][k] = 0.f;

    #pragma unroll
    for (int s = 0; s < NSTAGE - 1; s++) {
        uint32_t so = s * 32768;
        #pragma unroll
        for (int u = 0; u < 8; u++) {
            CP_ASYNC16(dA0 + so + u * 2048, srcA + (size_t)(s * 64) + (size_t)u * 16 * K);
            CP_ASYNC16(dB0 + so + u * 2048, srcB + (size_t)(s * 64) + (size_t)u * 16 * K);
        }
        CP_COMMIT();
    }

    for (int c = 0; c < nc; c++) {
        CP_WAIT1();
        __syncthreads();
        int nstg = c + NSTAGE - 1;
        if (nstg < nc) {
            uint32_t so = (nstg % NSTAGE) * 32768;
            #pragma unroll
            for (int u = 0; u < 8; u++) {
                CP_ASYNC16(dA0 + so + u * 2048, srcA + (size_t)(nstg * 64) + (size_t)u * 16 * K);
                CP_ASYNC16(dB0 + so + u * 2048, srcB + (size_t)(nstg * 64) + (size_t)u * 16 * K);
            }
        }
        CP_COMMIT();

        uint32_t so = (c % NSTAGE) * 32768;
        #pragma unroll
        for (int ks = 0; ks < 4; ks++) {
            uint32_t segA = ((2 * ks + qhA) ^ xA) << 4;
            uint32_t segB = ((2 * ks + qhB) ^ xB) << 4;
            uint32_t a[4][4];
            #pragma unroll
            for (int mi = 0; mi < 4; mi++)
                ldsm4(a[mi], baseA + so + mi * 2048 + segA);
            #pragma unroll
            for (int p = 0; p < 4; p++) {
                uint32_t br[4];
                ldsm4(br, baseB + so + p * 2048 + segB);
                #pragma unroll
                for (int mi = 0; mi < 4; mi++) {
                    mma_f16(acc[mi][2 * p + 0], a[mi][0], a[mi][1], a[mi][2], a[mi][3], br[0], br[1]);
                    mma_f16(acc[mi][2 * p + 1], a[mi][0], a[mi][1], a[mi][2], a[mi][3], br[2], br[3]);
                }
            }
        }
    }

    bool vtile = VTOUT && (col0 >= 1536);
    #pragma unroll
    for (int mi = 0; mi < 4; mi++) {
        int rr = row0 + m0 + 16 * mi + r;
        #pragma unroll
        for (int nj = 0; nj < 8; nj++) {
            int cc = col0 + n0 + 8 * nj + 2 * l;
            float b0 = bias[cc], b1 = bias[cc + 1];
            float v0 = acc[mi][nj][0] + b0;
            float v1 = acc[mi][nj][1] + b1;
            float v2 = acc[mi][nj][2] + b0;
            float v3 = acc[mi][nj][3] + b1;
            if (EPI == 1) {
                const float* rp0 = res + (size_t)rr * N + cc;
                const float* rp1 = res + (size_t)(rr + 8) * N + cc;
                v0 += rp0[0]; v1 += rp0[1];
                v2 += rp1[0]; v3 += rp1[1];
            }
            if (EPI == 2) {
                v0 = 0.5f * v0 * (1.f + erff(v0 * 0.70710678118654752f));
                v1 = 0.5f * v1 * (1.f + erff(v1 * 0.70710678118654752f));
                v2 = 0.5f * v2 * (1.f + erff(v2 * 0.70710678118654752f));
                v3 = 0.5f * v3 * (1.f + erff(v3 * 0.70710678118654752f));
            }
            if (VTOUT) {
                if (vtile) {
                    int d = cc - 1536;
                    int hh = d >> 6, dl = d & 63;
                    int b = rr >> 10, j = rr & 1023;
                    __half* vp = Vtp + ((size_t)(b * HH + hh) * 64 + dl) * LL + j;
                    vp[0] = __float2half(v0);
                    vp[LL] = __float2half(v1);
                    vp[8] = __float2half(v2);
                    vp[LL + 8] = __float2half(v3);
                    continue;
                }
            }
            if (HALFOUT) {
                __half* Ch = (__half*)Cv;
                *(__half2*)(Ch + (size_t)rr * N + cc) = __floats2half2_rn(v0, v1);
                *(__half2*)(Ch + (size_t)(rr + 8) * N + cc) = __floats2half2_rn(v2, v3);
            } else {
                float* Cf = (float*)Cv;
                float2 o01 = { v0, v1 };
                float2 o23 = { v2, v3 };
                *(float2*)(Cf + (size_t)rr * N + cc) = o01;
                *(float2*)(Cf + (size_t)(rr + 8) * N + cc) = o23;
            }
        }
    }
}

// ======= fp16 flash attention: R12 structure, register-resident P ==========
// smem: Q 16KB | K 8KB | V^T 8KB | tables (single-buffered, as R12)
#define ATB_QS 0
#define ATB_KS 16384
#define ATB_VT 24576
#define ATB_TB 32768
#define TB_REL  0
#define TB_PT   513
#define TB_LEX  1537    // [64]
#define TB_PIDQ 1601    // int [128]
#define TB_PIDK 1729    // int [64]
#define TB_END  1793
#define ATTN_SMEM (ATB_TB + TB_END * 4)   // 39940

__global__ __launch_bounds__(256, 2) void attn_mma(
    const __half* __restrict__ QKV, const __half* __restrict__ Vt,
    const float* __restrict__ rel_emb, const float* __restrict__ ptab,
    const int* __restrict__ pids, const float* __restrict__ lex,
    __half* __restrict__ ctx) {
    char* sb = smem_raw;
    float* tb = (float*)(sb + ATB_TB);
    int* tbi = (int*)tb;
    uint32_t sbase = smem_u32(sb);
    const float LOG2E = 1.44269504089f;

    int tid = threadIdx.x;
    int w = tid >> 5, lane = tid & 31;
    int r = lane >> 2, l = lane & 3;
    int quad = lane >> 3, qr = lane & 7;
    int h = blockIdx.y, bbx = blockIdx.z;
    int i0 = blockIdx.x * 128;

    for (int i = tid; i < 513; i += 256) tb[TB_REL + i] = rel_emb[i * HH + h];
    for (int i = tid; i < 1024; i += 256) tb[TB_PT + i] = ptab[i * HH + h];
    if (tid < 128) tbi[TB_PIDQ + tid] = pids[bbx * LL + i0 + tid];
    // Q tile: scale by 1/8, store swizzled
    {
        __half2 sc = __float2half2_rn(0.125f);
        #pragma unroll
        for (int u = 0; u < 4; u++) {
            int idx = u * 256 + tid;
            int row = idx >> 3, seg = idx & 7;
            const __half2* src = (const __half2*)(QKV + (size_t)(bbx * LL + i0 + row) * QKVS + h * 64 + seg * 8);
            __half2 v0 = __hmul2(src[0], sc), v1 = __hmul2(src[1], sc);
            __half2 v2 = __hmul2(src[2], sc), v3 = __hmul2(src[3], sc);
            uint4 pk = { h2u(v0), h2u(v1), h2u(v2), h2u(v3) };
            *(uint4*)(sb + ATB_QS + row * 128 + ((seg ^ (row & 7)) << 4)) = pk;
        }
    }
    __syncthreads();

    // Q A-frags resident
    uint32_t aq[4][4];
    {
        int rowA = w * 16 + ((quad & 1) << 3) + qr;
        int xA = rowA & 7, qh = quad >> 1;
        uint32_t baseA = sbase + ATB_QS + rowA * 128;
        #pragma unroll
        for (int ks = 0; ks < 4; ks++)
            ldsm4(aq[ks], baseA + (((2 * ks + qh) ^ xA) << 4));
    }
    int pq0 = tbi[TB_PIDQ + w * 16 + r] * PP;
    int pq1 = tbi[TB_PIDQ + w * 16 + r + 8] * PP;

    float o[8][4];
    #pragma unroll
    for (int nj = 0; nj < 8; nj++)
        #pragma unroll
        for (int k = 0; k < 4; k++) o[nj][k] = 0.f;

    // B-frag row pattern for K and V
    int rowK = ((quad >> 1) << 3) + qr;
    int xK = rowK & 7, qhK = quad & 1;
    uint32_t baseK = sbase + ATB_KS + rowK * 128;
    uint32_t baseV = sbase + ATB_VT + rowK * 128;

    // softmax state in registers (lane-replicated within each quad-pair group)
    float m0v = -1e30f, m1v = -1e30f, ls0 = 0.f, ls1 = 0.f;

    for (int t = 0; t < 16; t++) {
        int j0 = t * 64;
        // cp.async K + V^T tiles (single buffer, R12 pattern)
        #pragma unroll
        for (int u = 0; u < 2; u++) {
            int idx = u * 256 + tid;
            int row = idx >> 3, seg = idx & 7;
            uint32_t sw = row * 128 + ((seg ^ (row & 7)) << 4);
            CP_ASYNC16(sbase + ATB_KS + sw,
                       QKV + (size_t)(bbx * LL + j0 + row) * QKVS + 768 + h * 64 + seg * 8);
            CP_ASYNC16(sbase + ATB_VT + sw,
                       Vt + ((size_t)(bbx * HH + h) * 64 + row) * LL + j0 + seg * 8);
        }
        CP_COMMIT();
        if (tid < 64) {
            tbi[TB_PIDK + tid] = pids[bbx * LL + j0 + tid];
            tb[TB_LEX + tid] = lex[bbx * LL + j0 + tid];
        }
        CP_WAIT0();
        __syncthreads();

        // S = Q @ K^T
        float s[8][4];
        #pragma unroll
        for (int nj = 0; nj < 8; nj++)
            #pragma unroll
            for (int k = 0; k < 4; k++) s[nj][k] = 0.f;
        #pragma unroll
        for (int ks = 0; ks < 4; ks++) {
            #pragma unroll
            for (int p = 0; p < 4; p++) {
                uint32_t br[4];
                ldsm4(br, baseK + p * 2048 + (((2 * ks + qhK) ^ xK) << 4));
                mma_f16(s[2 * p + 0], aq[ks][0], aq[ks][1], aq[ks][2], aq[ks][3], br[0], br[1]);
                mma_f16(s[2 * p + 1], aq[ks][0], aq[ks][1], aq[ks][2], aq[ks][3], br[2], br[3]);
            }
        }

        // biases + row max
        int rg0 = i0 + w * 16 + r, rg1 = rg0 + 8;
        float mx0 = -1e30f, mx1 = -1e30f;
        #pragma unroll
        for (int nj = 0; nj < 8; nj++) {
            int ca = nj * 8 + 2 * l;
            int jga = j0 + ca;
            int pka = tbi[TB_PIDK + ca], pkb = tbi[TB_PIDK + ca + 1];
            float lxa = tb[TB_LEX + ca], lxb = tb[TB_LEX + ca + 1];
            int ra0 = min(max(jga - rg0, -MAXD_), MAXD_) + MAXD_;
            int rb0 = min(max(jga + 1 - rg0, -MAXD_), MAXD_) + MAXD_;
            int ra1 = min(max(jga - rg1, -MAXD_), MAXD_) + MAXD_;
            int rb1 = min(max(jga + 1 - rg1, -MAXD_), MAXD_) + MAXD_;
            s[nj][0] += tb[TB_REL + ra0] + tb[TB_PT + pq0 + pka] + lxa;
            s[nj][1] += tb[TB_REL + rb0] + tb[TB_PT + pq0 + pkb] + lxb;
            s[nj][2] += tb[TB_REL + ra1] + tb[TB_PT + pq1 + pka] + lxa;
            s[nj][3] += tb[TB_REL + rb1] + tb[TB_PT + pq1 + pkb] + lxb;
            mx0 = fmaxf(mx0, fmaxf(s[nj][0], s[nj][1]));
            mx1 = fmaxf(mx1, fmaxf(s[nj][2], s[nj][3]));
        }
        mx0 = fmaxf(mx0, __shfl_xor_sync(0xffffffffu, mx0, 1));
        mx0 = fmaxf(mx0, __shfl_xor_sync(0xffffffffu, mx0, 2));
        mx1 = fmaxf(mx1, __shfl_xor_sync(0xffffffffu, mx1, 1));
        mx1 = fmaxf(mx1, __shfl_xor_sync(0xffffffffu, mx1, 2));

        float mn0 = fmaxf(m0v, mx0), mn1 = fmaxf(m1v, mx1);
        float al0 = exp2f((m0v - mn0) * LOG2E), al1 = exp2f((m1v - mn1) * LOG2E);
        m0v = mn0; m1v = mn1;

        // exp via ex2.f16x2 -> packed half2 = PV A-fragments directly
        uint32_t ph0[8], ph1[8];
        float sum0 = 0.f, sum1 = 0.f;
        #pragma unroll
        for (int nj = 0; nj < 8; nj++) {
            float t0 = (s[nj][0] - mn0) * LOG2E;
            float t1 = (s[nj][1] - mn0) * LOG2E;
            float t2 = (s[nj][2] - mn1) * LOG2E;
            float t3 = (s[nj][3] - mn1) * LOG2E;
            ph0[nj] = pack_ex2_h2(t1, t0);
            ph1[nj] = pack_ex2_h2(t3, t2);
            float2 f0 = __half22float2(*(__half2*)&ph0[nj]);
            float2 f1 = __half22float2(*(__half2*)&ph1[nj]);
            sum0 += f0.x + f0.y;
            sum1 += f1.x + f1.y;
            o[nj][0] *= al0; o[nj][1] *= al0; o[nj][2] *= al1; o[nj][3] *= al1;
        }
        sum0 += __shfl_xor_sync(0xffffffffu, sum0, 1);
        sum0 += __shfl_xor_sync(0xffffffffu, sum0, 2);
        sum1 += __shfl_xor_sync(0xffffffffu, sum1, 1);
        sum1 += __shfl_xor_sync(0xffffffffu, sum1, 2);
        ls0 = ls0 * al0 + sum0;
        ls1 = ls1 * al1 + sum1;

        // O += P @ V (P fragments straight from registers)
        #pragma unroll
        for (int kg = 0; kg < 4; kg++) {
            uint32_t a0 = ph0[2 * kg], a1 = ph1[2 * kg];
            uint32_t a2 = ph0[2 * kg + 1], a3 = ph1[2 * kg + 1];
            #pragma unroll
            for (int p = 0; p < 4; p++) {
                uint32_t bv[4];
                ldsm4(bv, baseV + p * 2048 + (((2 * kg + qhK) ^ xK) << 4));
                mma_f16(o[2 * p + 0], a0, a1, a2, a3, bv[0], bv[1]);
                mma_f16(o[2 * p + 1], a0, a1, a2, a3, bv[2], bv[3]);
            }
        }
        __syncthreads();
    }

    // finalize
    float inv0 = 1.f / ls0;
    float inv1 = 1.f / ls1;
    int row0g = bbx * LL + i0 + w * 16 + r;
    #pragma unroll
    for (int nj = 0; nj < 8; nj++) {
        *(__half2*)(ctx + (size_t)row0g * DD + h * 64 + nj * 8 + 2 * l)
            = __floats2half2_rn(o[nj][0] * inv0, o[nj][1] * inv0);
        *(__half2*)(ctx + (size_t)(row0g + 8) * DD + h * 64 + nj * 8 + 2 * l)
            = __floats2half2_rn(o[nj][2] * inv1, o[nj][3] * inv1);
    }
}

// ---------------- launch ----------------
extern "C" void kernel_launch(void* const* d_in, const int* in_sizes, int n_in,
                              void* d_out, int out_size) {
    const float* x      = (const float*)d_in[0];
    const int*   postag = (const int*)  d_in[1];
    const float* lexm   = (const float*)d_in[2];
    const float* ln1g   = (const float*)d_in[3];
    const float* ln1b   = (const float*)d_in[4];
    const float* Wq     = (const float*)d_in[5];
    const float* bq     = (const float*)d_in[6];
    const float* Wk     = (const float*)d_in[7];
    const float* bk     = (const float*)d_in[8];
    const float* Wv     = (const float*)d_in[9];
    const float* bv     = (const float*)d_in[10];
    const float* Wo     = (const float*)d_in[11];
    const float* bo     = (const float*)d_in[12];
    const float* rel    = (const float*)d_in[13];
    const float* ptab   = (const float*)d_in[14];
    const float* ln2g   = (const float*)d_in[15];
    const float* ln2b   = (const float*)d_in[16];
    const float* W1     = (const float*)d_in[17];
    const float* b1     = (const float*)d_in[18];
    const float* W2     = (const float*)d_in[19];
    const float* b2     = (const float*)d_in[20];
    float* out = (float*)d_out;

    __half *qin, *QKVb, *Vt, *ctx, *h2, *ff;
    __half *WqkvT, *WoT, *W1T, *W2T;
    float *res1, *bqkv;
    cudaGetSymbolAddress((void**)&qin,   g_qin);
    cudaGetSymbolAddress((void**)&QKVb,  g_QKV);
    cudaGetSymbolAddress((void**)&Vt,    g_Vt);
    cudaGetSymbolAddress((void**)&ctx,   g_ctx);
    cudaGetSymbolAddress((void**)&res1,  g_res1);
    cudaGetSymbolAddress((void**)&h2,    g_h2);
    cudaGetSymbolAddress((void**)&ff,    g_ff);
    cudaGetSymbolAddress((void**)&WqkvT, g_WqkvT);
    cudaGetSymbolAddress((void**)&bqkv,  g_bqkv);
    cudaGetSymbolAddress((void**)&WoT,   g_WoT);
    cudaGetSymbolAddress((void**)&W1T,   g_W1T);
    cudaGetSymbolAddress((void**)&W2T,   g_W2T);

    cudaFuncSetAttribute(attn_mma, cudaFuncAttributeMaxDynamicSharedMemorySize, ATTN_SMEM);
    cudaFuncSetAttribute(mma_gemm<0,1,1>, cudaFuncAttributeMaxDynamicSharedMemorySize, GSMEM);
    cudaFuncSetAttribute(mma_gemm<1,0,0>, cudaFuncAttributeMaxDynamicSharedMemorySize, GSMEM);
    cudaFuncSetAttribute(mma_gemm<2,1,0>, cudaFuncAttributeMaxDynamicSharedMemorySize, GSMEM);

    // 0: QKV weight transpose
    transpose_wqkv<<<1728, dim3(32, 8)>>>(Wq, Wk, Wv, bq, bk, bv, WqkvT, bqkv);
    // 1: other weight transposes
    transpose_wrest<<<5184, dim3(32, 8)>>>(Wo, W1, W2, WoT, W1T, W2T);
    // 2: LN1 -> fp16
    ln_kernel<<<ML, 256>>>(x, ln1g, ln1b, qin, 1e-6f);
    // 3: fused QKV projection (V written transposed to Vt)  <- ncu capture
    mma_gemm<0,1,1><<<dim3(QKVS / 128, ML / 128), 128, GSMEM>>>(qin, WqkvT, bqkv, nullptr, QKVb, Vt, DD, QKVS);
    // 4: attention
    attn_mma<<<dim3(LL / 128, HH, BB), 256, ATTN_SMEM>>>(QKVb, Vt, rel, ptab, postag, lexm, ctx);
    // 5: output projection + residual
    mma_gemm<1,0,0><<<dim3(DD / 128, ML / 128), 128, GSMEM>>>(ctx, WoT, bo, x, res1, nullptr, DD, DD);
    // 6: LN2 -> fp16
    ln_kernel<<<ML, 256>>>(res1, ln2g, ln2b, h2, 1e-5f);
    // 7: FFN up + GELU
    mma_gemm<2,1,0><<<dim3(FF_ / 128, ML / 128), 128, GSMEM>>>(h2, W1T, b1, nullptr, ff, nullptr, DD, FF_);
    // 8: FFN down + bias + residual -> out
    mma_gemm<1,0,0><<<dim3(DD / 128, ML / 128), 128, GSMEM>>>(ff, W2T, b2, res1, out, nullptr, FF_, DD);
}

// round 16
// speedup vs baseline: 1.5508x; 1.0119x over previous
#include <cuda_runtime.h>
#include <cuda_fp16.h>
#include <math.h>
#include <stdint.h>

// Problem constants
#define BB   4
#define LL   1024
#define DD   768
#define HH   12
#define FF_  3072
#define PP   32
#define MAXD_ 256
#define ML   (BB*LL)   // 4096 rows
#define QKVS 2304      // fused QKV row stride

// ---------------- scratch (device globals; no runtime allocation) ----------
__device__ __half g_qin[ML*DD];
__device__ __half g_QKV[ML*QKVS];
__device__ __half g_Vt[(size_t)BB*HH*64*LL];   // [b][h][d][j]
__device__ __half g_ctx[ML*DD];
__device__ float  g_res1[ML*DD];
__device__ __half g_h2[ML*DD];
__device__ __half g_ff[ML*FF_];
// transposed weights [N,K] fp16
__device__ __half g_WqkvT[QKVS*DD];
__device__ float  g_bqkv[QKVS];
__device__ __half g_WoT[DD*DD];
__device__ __half g_W1T[FF_*DD];
__device__ __half g_W2T[DD*FF_];

// single extern shared symbol for all kernels
extern __shared__ char smem_raw[];

// ======================= helpers =====================
__device__ __forceinline__ uint32_t smem_u32(const void* p) {
    uint32_t a;
    asm("{ .reg .u64 t; cvta.to.shared.u64 t, %1; cvt.u32.u64 %0, t; }" : "=r"(a) : "l"(p));
    return a;
}

#define CP_ASYNC16(dst, src) \
    asm volatile("cp.async.ca.shared.global [%0], [%1], 16;" :: "r"(dst), "l"(src) : "memory")
#define CP_COMMIT()  asm volatile("cp.async.commit_group;" ::: "memory")
#define CP_WAIT1()   asm volatile("cp.async.wait_group 1;" ::: "memory")
#define CP_WAIT0()   asm volatile("cp.async.wait_group 0;" ::: "memory")

__device__ __forceinline__ void mma_f16(float c[4], uint32_t a0, uint32_t a1,
                                        uint32_t a2, uint32_t a3,
                                        uint32_t b0, uint32_t b1) {
    asm volatile(
        "mma.sync.aligned.m16n8k16.row.col.f32.f16.f16.f32 "
        "{%0,%1,%2,%3}, {%4,%5,%6,%7}, {%8,%9}, {%0,%1,%2,%3};"
        : "+f"(c[0]), "+f"(c[1]), "+f"(c[2]), "+f"(c[3])
        : "r"(a0), "r"(a1), "r"(a2), "r"(a3), "r"(b0), "r"(b1));
}
__device__ __forceinline__ void ldsm4(uint32_t r[4], uint32_t addr) {
    asm volatile("ldmatrix.sync.aligned.m8n8.x4.shared.b16 {%0,%1,%2,%3}, [%4];"
                 : "=r"(r[0]), "=r"(r[1]), "=r"(r[2]), "=r"(r[3]) : "r"(addr));
}
__device__ __forceinline__ uint32_t h2u(__half2 h) { return *(uint32_t*)&h; }

// pack two floats into half2 (lo, hi) and apply ex2 elementwise
__device__ __forceinline__ uint32_t pack_ex2_h2(float hi, float lo) {
    uint32_t d;
    asm("cvt.rn.f16x2.f32 %0, %1, %2;" : "=r"(d) : "f"(hi), "f"(lo));
    asm("ex2.approx.f16x2 %0, %0;" : "+r"(d));
    return d;
}

// ---------------- transpose kernels (fp16 out) -----------------------------
__global__ void transpose_wqkv(const float* __restrict__ Wq, const float* __restrict__ Wk,
                               const float* __restrict__ Wv, const float* __restrict__ bq,
                               const float* __restrict__ bk, const float* __restrict__ bv,
                               __half* __restrict__ WqkvT, float* __restrict__ bqkv) {
    __shared__ float t[32][33];
    int idx = blockIdx.x;
    int z = idx / 576, lo = idx % 576;
    const float* src = (z == 0) ? Wq : (z == 1) ? Wk : Wv;
    size_t dstoff = (size_t)z * DD * DD;
    int bx = lo % 24, by = lo / 24;
    int c0 = bx * 32, r0 = by * 32;
    int x = threadIdx.x, y = threadIdx.y;
    #pragma unroll
    for (int i = 0; i < 32; i += 8)
        t[y + i][x] = src[(size_t)(r0 + y + i) * DD + c0 + x];
    __syncthreads();
    #pragma unroll
    for (int i = 0; i < 32; i += 8)
        WqkvT[dstoff + (size_t)(c0 + y + i) * DD + r0 + x] = __float2half(t[x][y + i]);
    if (idx == 0) {
        int tid = y * 32 + x;
        for (int i = tid; i < QKVS; i += 256)
            bqkv[i] = (i < 768) ? bq[i] : (i < 1536) ? bk[i - 768] : bv[i - 1536];
    }
}

__global__ void transpose_wrest(const float* __restrict__ Wo, const float* __restrict__ W1,
                                const float* __restrict__ W2,
                                __half* __restrict__ WoT, __half* __restrict__ W1T,
                                __half* __restrict__ W2T) {
    __shared__ float t[32][33];
    int idx = blockIdx.x;
    const float* src; __half* dst; int R, C, bx, by;
    if (idx < 576) {
        src = Wo; dst = WoT; R = DD; C = DD; bx = idx % 24; by = idx / 24;
    } else if (idx < 2880) {
        int lo = idx - 576; src = W1; dst = W1T; R = DD; C = FF_; bx = lo % 96; by = lo / 96;
    } else {
        int lo = idx - 2880; src = W2; dst = W2T; R = FF_; C = DD; bx = lo % 24; by = lo / 24;
    }
    int c0 = bx * 32, r0 = by * 32;
    int x = threadIdx.x, y = threadIdx.y;
    #pragma unroll
    for (int i = 0; i < 32; i += 8)
        t[y + i][x] = src[(size_t)(r0 + y + i) * C + c0 + x];
    __syncthreads();
    #pragma unroll
    for (int i = 0; i < 32; i += 8)
        dst[(size_t)(c0 + y + i) * R + r0 + x] = __float2half(t[x][y + i]);
}

// ---------------- LayerNorm (fp16 output) ----------------
__global__ void ln_kernel(const float* __restrict__ x, const float* __restrict__ g,
                          const float* __restrict__ b, __half* __restrict__ y, float eps) {
    int row = blockIdx.x;
    const float* xr = x + (size_t)row * DD;
    __shared__ float red[256];
    int tid = threadIdx.x;

    float s = 0.f;
    for (int d = tid; d < DD; d += 256) s += xr[d];
    red[tid] = s; __syncthreads();
    #pragma unroll
    for (int o = 128; o > 0; o >>= 1) { if (tid < o) red[tid] += red[tid + o]; __syncthreads(); }
    float mu = red[0] * (1.f / DD);
    __syncthreads();

    float v = 0.f;
    for (int d = tid; d < DD; d += 256) { float t = xr[d] - mu; v += t * t; }
    red[tid] = v; __syncthreads();
    #pragma unroll
    for (int o = 128; o > 0; o >>= 1) { if (tid < o) red[tid] += red[tid + o]; __syncthreads(); }
    float inv = rsqrtf(red[0] * (1.f / DD) + eps);

    __half* yr = y + (size_t)row * DD;
    for (int d = tid; d < DD; d += 256)
        yr[d] = __float2half((xr[d] - mu) * inv * g[d] + b[d]);
}

// ====== fp16 mma GEMM, 64x64 warp tiles (unchanged from R12/R15) ===========
#define NSTAGE 3
#define GSMEM (NSTAGE * 32768)   // 96KB

template<int EPI, int HALFOUT, int VTOUT>
__global__ __launch_bounds__(128, 2) void mma_gemm(
    const __half* __restrict__ A, const __half* __restrict__ Bt,
    const float* __restrict__ bias, const float* __restrict__ res,
    void* __restrict__ Cv, __half* __restrict__ Vtp, int K, int N) {
    uint32_t smem_base = smem_u32(smem_raw);

    int tid = threadIdx.x;
    int wid = tid >> 5, lane = tid & 31;
    int r = lane >> 2, l = lane & 3;
    int quad = lane >> 3, qr = lane & 7;
    int row0 = blockIdx.y * 128, col0 = blockIdx.x * 128;
    int m0 = (wid & 1) * 64, n0 = (wid >> 1) * 64;

    int m_l = tid >> 3, s_l = tid & 7;
    const __half* srcA = A + (size_t)(row0 + m_l) * K + s_l * 8;
    const __half* srcB = Bt + (size_t)(col0 + m_l) * K + s_l * 8;
    uint32_t dA0 = smem_base + m_l * 128 + ((s_l ^ (m_l & 7)) << 4);
    uint32_t dB0 = dA0 + 16384;

    int arow = m0 + ((quad & 1) << 3) + qr;
    int xA = arow & 7, qhA = quad >> 1;
    uint32_t baseA = smem_base + arow * 128;
    int brow = n0 + ((quad >> 1) << 3) + qr;
    int xB = brow & 7, qhB = quad & 1;
    uint32_t baseB = smem_base + 16384 + brow * 128;

    int nc = K >> 6;

    float acc[4][8][4];
    #pragma unroll
    for (int i = 0; i < 4; i++)
        #pragma unroll
        for (int j = 0; j < 8; j++)
            #pragma unroll
            for (int k = 0; k < 4; k++) acc[i][j][k] = 0.f;

    #pragma unroll
    for (int s = 0; s < NSTAGE - 1; s++) {
        uint32_t so = s * 32768;
        #pragma unroll
        for (int u = 0; u < 8; u++) {
            CP_ASYNC16(dA0 + so + u * 2048, srcA + (size_t)(s * 64) + (size_t)u * 16 * K);
            CP_ASYNC16(dB0 + so + u * 2048, srcB + (size_t)(s * 64) + (size_t)u * 16 * K);
        }
        CP_COMMIT();
    }

    for (int c = 0; c < nc; c++) {
        CP_WAIT1();
        __syncthreads();
        int nstg = c + NSTAGE - 1;
        if (nstg < nc) {
            uint32_t so = (nstg % NSTAGE) * 32768;
            #pragma unroll
            for (int u = 0; u < 8; u++) {
                CP_ASYNC16(dA0 + so + u * 2048, srcA + (size_t)(nstg * 64) + (size_t)u * 16 * K);
                CP_ASYNC16(dB0 + so + u * 2048, srcB + (size_t)(nstg * 64) + (size_t)u * 16 * K);
            }
        }
        CP_COMMIT();

        uint32_t so = (c % NSTAGE) * 32768;
        #pragma unroll
        for (int ks = 0; ks < 4; ks++) {
            uint32_t segA = ((2 * ks + qhA) ^ xA) << 4;
            uint32_t segB = ((2 * ks + qhB) ^ xB) << 4;
            uint32_t a[4][4];
            #pragma unroll
            for (int mi = 0; mi < 4; mi++)
                ldsm4(a[mi], baseA + so + mi * 2048 + segA);
            #pragma unroll
            for (int p = 0; p < 4; p++) {
                uint32_t br[4];
                ldsm4(br, baseB + so + p * 2048 + segB);
                #pragma unroll
                for (int mi = 0; mi < 4; mi++) {
                    mma_f16(acc[mi][2 * p + 0], a[mi][0], a[mi][1], a[mi][2], a[mi][3], br[0], br[1]);
                    mma_f16(acc[mi][2 * p + 1], a[mi][0], a[mi][1], a[mi][2], a[mi][3], br[2], br[3]);
                }
            }
        }
    }

    bool vtile = VTOUT && (col0 >= 1536);
    #pragma unroll
    for (int mi = 0; mi < 4; mi++) {
        int rr = row0 + m0 + 16 * mi + r;
        #pragma unroll
        for (int nj = 0; nj < 8; nj++) {
            int cc = col0 + n0 + 8 * nj + 2 * l;
            float b0 = bias[cc], b1 = bias[cc + 1];
            float v0 = acc[mi][nj][0] + b0;
            float v1 = acc[mi][nj][1] + b1;
            float v2 = acc[mi][nj][2] + b0;
            float v3 = acc[mi][nj][3] + b1;
            if (EPI == 1) {
                const float* rp0 = res + (size_t)rr * N + cc;
                const float* rp1 = res + (size_t)(rr + 8) * N + cc;
                v0 += rp0[0]; v1 += rp0[1];
                v2 += rp1[0]; v3 += rp1[1];
            }
            if (EPI == 2) {
                v0 = 0.5f * v0 * (1.f + erff(v0 * 0.70710678118654752f));
                v1 = 0.5f * v1 * (1.f + erff(v1 * 0.70710678118654752f));
                v2 = 0.5f * v2 * (1.f + erff(v2 * 0.70710678118654752f));
                v3 = 0.5f * v3 * (1.f + erff(v3 * 0.70710678118654752f));
            }
            if (VTOUT) {
                if (vtile) {
                    int d = cc - 1536;
                    int hh = d >> 6, dl = d & 63;
                    int b = rr >> 10, j = rr & 1023;
                    __half* vp = Vtp + ((size_t)(b * HH + hh) * 64 + dl) * LL + j;
                    vp[0] = __float2half(v0);
                    vp[LL] = __float2half(v1);
                    vp[8] = __float2half(v2);
                    vp[LL + 8] = __float2half(v3);
                    continue;
                }
            }
            if (HALFOUT) {
                __half* Ch = (__half*)Cv;
                *(__half2*)(Ch + (size_t)rr * N + cc) = __floats2half2_rn(v0, v1);
                *(__half2*)(Ch + (size_t)(rr + 8) * N + cc) = __floats2half2_rn(v2, v3);
            } else {
                float* Cf = (float*)Cv;
                float2 o01 = { v0, v1 };
                float2 o23 = { v2, v3 };
                *(float2*)(Cf + (size_t)rr * N + cc) = o01;
                *(float2*)(Cf + (size_t)(rr + 8) * N + cc) = o23;
            }
        }
    }
}

// ======= fp16 flash attention: register P, paired 128-col K/V loads ========
// smem bytes: Q 16KB | K [128 j][64 d] 16KB | V^T 2x[64 d][64 j] 16KB | tables
#define ATB_QS 0
#define ATB_KS 16384
#define ATB_VT 32768
#define ATB_TB 49152
// table offsets in floats (all even -> int2/float2 aligned)
#define TB_RELX 0       // [2047] extended rel table, index = (j-i)+1023
#define TB_PT   2048    // [1024]
#define TB_LEX  3072    // [128] per 128-col pair
#define TB_PIDQ 3200    // int [128]
#define TB_PIDK 3328    // int [128] per pair
#define TB_END  3456
#define ATTN_SMEM (ATB_TB + TB_END * 4)   // 62976

__global__ __launch_bounds__(256, 2) void attn_mma(
    const __half* __restrict__ QKV, const __half* __restrict__ Vt,
    const float* __restrict__ rel_emb, const float* __restrict__ ptab,
    const int* __restrict__ pids, const float* __restrict__ lex,
    __half* __restrict__ ctx) {
    char* sb = smem_raw;
    float* tb = (float*)(sb + ATB_TB);
    int* tbi = (int*)tb;
    uint32_t sbase = smem_u32(sb);
    const float LOG2E = 1.44269504089f;

    int tid = threadIdx.x;
    int w = tid >> 5, lane = tid & 31;
    int r = lane >> 2, l = lane & 3;
    int quad = lane >> 3, qr = lane & 7;
    int h = blockIdx.y, bbx = blockIdx.z;
    int i0 = blockIdx.x * 128;

    // extended rel table: relx[d] = rel_emb[clamp(d-1023,-256,256)+256][h]
    for (int i = tid; i < 2047; i += 256) {
        int rr = min(max(i - 1023, -MAXD_), MAXD_) + MAXD_;
        tb[TB_RELX + i] = rel_emb[rr * HH + h];
    }
    for (int i = tid; i < 1024; i += 256) tb[TB_PT + i] = ptab[i * HH + h];
    if (tid < 128) tbi[TB_PIDQ + tid] = pids[bbx * LL + i0 + tid];
    // Q tile: scale by 1/8, store swizzled
    {
        __half2 sc = __float2half2_rn(0.125f);
        #pragma unroll
        for (int u = 0; u < 4; u++) {
            int idx = u * 256 + tid;
            int row = idx >> 3, seg = idx & 7;
            const __half2* src = (const __half2*)(QKV + (size_t)(bbx * LL + i0 + row) * QKVS + h * 64 + seg * 8);
            __half2 v0 = __hmul2(src[0], sc), v1 = __hmul2(src[1], sc);
            __half2 v2 = __hmul2(src[2], sc), v3 = __hmul2(src[3], sc);
            uint4 pk = { h2u(v0), h2u(v1), h2u(v2), h2u(v3) };
            *(uint4*)(sb + ATB_QS + row * 128 + ((seg ^ (row & 7)) << 4)) = pk;
        }
    }
    __syncthreads();

    // Q A-frags resident
    uint32_t aq[4][4];
    {
        int rowA = w * 16 + ((quad & 1) << 3) + qr;
        int xA = rowA & 7, qh = quad >> 1;
        uint32_t baseA = sbase + ATB_QS + rowA * 128;
        #pragma unroll
        for (int ks = 0; ks < 4; ks++)
            ldsm4(aq[ks], baseA + (((2 * ks + qh) ^ xA) << 4));
    }
    int pq0 = tbi[TB_PIDQ + w * 16 + r] * PP;
    int pq1 = tbi[TB_PIDQ + w * 16 + r + 8] * PP;

    float o[8][4];
    #pragma unroll
    for (int nj = 0; nj < 8; nj++)
        #pragma unroll
        for (int k = 0; k < 4; k++) o[nj][k] = 0.f;

    // B-frag row pattern for K and V
    int rowK = ((quad >> 1) << 3) + qr;
    int xK = rowK & 7, qhK = quad & 1;

    // softmax state in registers
    float m0v = -1e30f, m1v = -1e30f, ls0 = 0.f, ls1 = 0.f;
    int rg0 = i0 + w * 16 + r, rg1 = rg0 + 8;

    for (int tp = 0; tp < 8; tp++) {
        int j0p = tp * 128;
        // cp.async: K 128 rows, V^T two 64-col subtiles
        #pragma unroll
        for (int u = 0; u < 4; u++) {
            int idx = u * 256 + tid;
            int row = idx >> 3, seg = idx & 7;          // row 0..127
            uint32_t sw = ((seg ^ (row & 7)) << 4);
            CP_ASYNC16(sbase + ATB_KS + row * 128 + sw,
                       QKV + (size_t)(bbx * LL + j0p + row) * QKVS + 768 + h * 64 + seg * 8);
            int d = row & 63, sub = row >> 6;
            CP_ASYNC16(sbase + ATB_VT + sub * 8192 + d * 128 + ((seg ^ (d & 7)) << 4),
                       Vt + ((size_t)(bbx * HH + h) * 64 + d) * LL + j0p + sub * 64 + seg * 8);
        }
        CP_COMMIT();
        if (tid < 128) {
            tbi[TB_PIDK + tid] = pids[bbx * LL + j0p + tid];
            tb[TB_LEX + tid] = lex[bbx * LL + j0p + tid];
        }
        CP_WAIT0();
        __syncthreads();

        #pragma unroll
        for (int sub = 0; sub < 2; sub++) {
            int j0 = j0p + sub * 64;
            uint32_t bK = sbase + ATB_KS + sub * 8192 + rowK * 128;
            uint32_t bV = sbase + ATB_VT + sub * 8192 + rowK * 128;
            const float* lexS = tb + TB_LEX + sub * 64;
            const int* pidS = tbi + TB_PIDK + sub * 64;

            // S = Q @ K^T
            float s[8][4];
            #pragma unroll
            for (int nj = 0; nj < 8; nj++)
                #pragma unroll
                for (int k = 0; k < 4; k++) s[nj][k] = 0.f;
            #pragma unroll
            for (int ks = 0; ks < 4; ks++) {
                #pragma unroll
                for (int p = 0; p < 4; p++) {
                    uint32_t br[4];
                    ldsm4(br, bK + p * 2048 + (((2 * ks + qhK) ^ xK) << 4));
                    mma_f16(s[2 * p + 0], aq[ks][0], aq[ks][1], aq[ks][2], aq[ks][3], br[0], br[1]);
                    mma_f16(s[2 * p + 1], aq[ks][0], aq[ks][1], aq[ks][2], aq[ks][3], br[2], br[3]);
                }
            }

            // biases (extended rel table: no clamping) + row max
            int off0 = j0 - rg0 + 1023 + 2 * l;
            int off1 = off0 - 8;
            float mx0 = -1e30f, mx1 = -1e30f;
            #pragma unroll
            for (int nj = 0; nj < 8; nj++) {
                int ca = nj * 8 + 2 * l;
                int2 pk2 = *(const int2*)(pidS + ca);
                float2 lx2 = *(const float2*)(lexS + ca);
                float r00 = tb[TB_RELX + off0 + nj * 8];
                float r01 = tb[TB_RELX + off0 + nj * 8 + 1];
                float r10 = tb[TB_RELX + off1 + nj * 8];
                float r11 = tb[TB_RELX + off1 + nj * 8 + 1];
                s[nj][0] += r00 + tb[TB_PT + pq0 + pk2.x] + lx2.x;
                s[nj][1] += r01 + tb[TB_PT + pq0 + pk2.y] + lx2.y;
                s[nj][2] += r10 + tb[TB_PT + pq1 + pk2.x] + lx2.x;
                s[nj][3] += r11 + tb[TB_PT + pq1 + pk2.y] + lx2.y;
                mx0 = fmaxf(mx0, fmaxf(s[nj][0], s[nj][1]));
                mx1 = fmaxf(mx1, fmaxf(s[nj][2], s[nj][3]));
            }
            mx0 = fmaxf(mx0, __shfl_xor_sync(0xffffffffu, mx0, 1));
            mx0 = fmaxf(mx0, __shfl_xor_sync(0xffffffffu, mx0, 2));
            mx1 = fmaxf(mx1, __shfl_xor_sync(0xffffffffu, mx1, 1));
            mx1 = fmaxf(mx1, __shfl_xor_sync(0xffffffffu, mx1, 2));

            float mn0 = fmaxf(m0v, mx0), mn1 = fmaxf(m1v, mx1);
            float al0 = exp2f((m0v - mn0) * LOG2E), al1 = exp2f((m1v - mn1) * LOG2E);
            m0v = mn0; m1v = mn1;

            // exp via ex2.f16x2 -> packed half2 = PV A-fragments directly
            uint32_t ph0[8], ph1[8];
            float sum0 = 0.f, sum1 = 0.f;
            #pragma unroll
            for (int nj = 0; nj < 8; nj++) {
                float t0 = (s[nj][0] - mn0) * LOG2E;
                float t1 = (s[nj][1] - mn0) * LOG2E;
                float t2 = (s[nj][2] - mn1) * LOG2E;
                float t3 = (s[nj][3] - mn1) * LOG2E;
                ph0[nj] = pack_ex2_h2(t1, t0);
                ph1[nj] = pack_ex2_h2(t3, t2);
                float2 f0 = __half22float2(*(__half2*)&ph0[nj]);
                float2 f1 = __half22float2(*(__half2*)&ph1[nj]);
                sum0 += f0.x + f0.y;
                sum1 += f1.x + f1.y;
                o[nj][0] *= al0; o[nj][1] *= al0; o[nj][2] *= al1; o[nj][3] *= al1;
            }
            sum0 += __shfl_xor_sync(0xffffffffu, sum0, 1);
            sum0 += __shfl_xor_sync(0xffffffffu, sum0, 2);
            sum1 += __shfl_xor_sync(0xffffffffu, sum1, 1);
            sum1 += __shfl_xor_sync(0xffffffffu, sum1, 2);
            ls0 = ls0 * al0 + sum0;
            ls1 = ls1 * al1 + sum1;

            // O += P @ V (P fragments straight from registers)
            #pragma unroll
            for (int kg = 0; kg < 4; kg++) {
                uint32_t a0 = ph0[2 * kg], a1 = ph1[2 * kg];
                uint32_t a2 = ph0[2 * kg + 1], a3 = ph1[2 * kg + 1];
                #pragma unroll
                for (int p = 0; p < 4; p++) {
                    uint32_t bv[4];
                    ldsm4(bv, bV + p * 2048 + (((2 * kg + qhK) ^ xK) << 4));
                    mma_f16(o[2 * p + 0], a0, a1, a2, a3, bv[0], bv[1]);
                    mma_f16(o[2 * p + 1], a0, a1, a2, a3, bv[2], bv[3]);
                }
            }
        }
        __syncthreads();
    }

    // finalize
    float inv0 = 1.f / ls0;
    float inv1 = 1.f / ls1;
    int row0g = bbx * LL + i0 + w * 16 + r;
    #pragma unroll
    for (int nj = 0; nj < 8; nj++) {
        *(__half2*)(ctx + (size_t)row0g * DD + h * 64 + nj * 8 + 2 * l)
            = __floats2half2_rn(o[nj][0] * inv0, o[nj][1] * inv0);
        *(__half2*)(ctx + (size_t)(row0g + 8) * DD + h * 64 + nj * 8 + 2 * l)
            = __floats2half2_rn(o[nj][2] * inv1, o[nj][3] * inv1);
    }
}

// ---------------- launch ----------------
extern "C" void kernel_launch(void* const* d_in, const int* in_sizes, int n_in,
                              void* d_out, int out_size) {
    const float* x      = (const float*)d_in[0];
    const int*   postag = (const int*)  d_in[1];
    const float* lexm   = (const float*)d_in[2];
    const float* ln1g   = (const float*)d_in[3];
    const float* ln1b   = (const float*)d_in[4];
    const float* Wq     = (const float*)d_in[5];
    const float* bq     = (const float*)d_in[6];
    const float* Wk     = (const float*)d_in[7];
    const float* bk     = (const float*)d_in[8];
    const float* Wv     = (const float*)d_in[9];
    const float* bv     = (const float*)d_in[10];
    const float* Wo     = (const float*)d_in[11];
    const float* bo     = (const float*)d_in[12];
    const float* rel    = (const float*)d_in[13];
    const float* ptab   = (const float*)d_in[14];
    const float* ln2g   = (const float*)d_in[15];
    const float* ln2b   = (const float*)d_in[16];
    const float* W1     = (const float*)d_in[17];
    const float* b1     = (const float*)d_in[18];
    const float* W2     = (const float*)d_in[19];
    const float* b2     = (const float*)d_in[20];
    float* out = (float*)d_out;

    __half *qin, *QKVb, *Vt, *ctx, *h2, *ff;
    __half *WqkvT, *WoT, *W1T, *W2T;
    float *res1, *bqkv;
    cudaGetSymbolAddress((void**)&qin,   g_qin);
    cudaGetSymbolAddress((void**)&QKVb,  g_QKV);
    cudaGetSymbolAddress((void**)&Vt,    g_Vt);
    cudaGetSymbolAddress((void**)&ctx,   g_ctx);
    cudaGetSymbolAddress((void**)&res1,  g_res1);
    cudaGetSymbolAddress((void**)&h2,    g_h2);
    cudaGetSymbolAddress((void**)&ff,    g_ff);
    cudaGetSymbolAddress((void**)&WqkvT, g_WqkvT);
    cudaGetSymbolAddress((void**)&bqkv,  g_bqkv);
    cudaGetSymbolAddress((void**)&WoT,   g_WoT);
    cudaGetSymbolAddress((void**)&W1T,   g_W1T);
    cudaGetSymbolAddress((void**)&W2T,   g_W2T);

    cudaFuncSetAttribute(attn_mma, cudaFuncAttributeMaxDynamicSharedMemorySize, ATTN_SMEM);
    cudaFuncSetAttribute(mma_gemm<0,1,1>, cudaFuncAttributeMaxDynamicSharedMemorySize, GSMEM);
    cudaFuncSetAttribute(mma_gemm<1,0,0>, cudaFuncAttributeMaxDynamicSharedMemorySize, GSMEM);
    cudaFuncSetAttribute(mma_gemm<2,1,0>, cudaFuncAttributeMaxDynamicSharedMemorySize, GSMEM);

    // 0: QKV weight transpose
    transpose_wqkv<<<1728, dim3(32, 8)>>>(Wq, Wk, Wv, bq, bk, bv, WqkvT, bqkv);
    // 1: other weight transposes
    transpose_wrest<<<5184, dim3(32, 8)>>>(Wo, W1, W2, WoT, W1T, W2T);
    // 2: LN1 -> fp16
    ln_kernel<<<ML, 256>>>(x, ln1g, ln1b, qin, 1e-6f);
    // 3: fused QKV projection (V written transposed to Vt)  <- ncu capture
    mma_gemm<0,1,1><<<dim3(QKVS / 128, ML / 128), 128, GSMEM>>>(qin, WqkvT, bqkv, nullptr, QKVb, Vt, DD, QKVS);
    // 4: attention
    attn_mma<<<dim3(LL / 128, HH, BB), 256, ATTN_SMEM>>>(QKVb, Vt, rel, ptab, postag, lexm, ctx);
    // 5: output projection + residual
    mma_gemm<1,0,0><<<dim3(DD / 128, ML / 128), 128, GSMEM>>>(ctx, WoT, bo, x, res1, nullptr, DD, DD);
    // 6: LN2 -> fp16
    ln_kernel<<<ML, 256>>>(res1, ln2g, ln2b, h2, 1e-5f);
    // 7: FFN up + GELU
    mma_gemm<2,1,0><<<dim3(FF_ / 128, ML / 128), 128, GSMEM>>>(h2, W1T, b1, nullptr, ff, nullptr, DD, FF_);
    // 8: FFN down + bias + residual -> out
    mma_gemm<1,0,0><<<dim3(DD / 128, ML / 128), 128, GSMEM>>>(ff, W2T, b2, res1, out, nullptr, FF_, DD);
}

// round 17
// speedup vs baseline: 1.6547x; 1.0670x over previous
#include <cuda_runtime.h>
#include <cuda_fp16.h>
#include <math.h>
#include <stdint.h>

// Problem constants
#define BB   4
#define LL   1024
#define DD   768
#define HH   12
#define FF_  3072
#define PP   32
#define MAXD_ 256
#define ML   (BB*LL)   // 4096 rows
#define QKVS 2304      // fused QKV row stride

// ---------------- scratch (device globals; no runtime allocation) ----------
__device__ __half g_qin[ML*DD];
__device__ __half g_QKV[ML*QKVS];
__device__ __half g_Vt[(size_t)BB*HH*64*LL];   // [b][h][d][j]
__device__ __half g_ctx[ML*DD];
__device__ float  g_res1[ML*DD];
__device__ __half g_h2[ML*DD];
__device__ __half g_ff[ML*FF_];
// transposed weights [N,K] fp16
__device__ __half g_WqkvT[QKVS*DD];
__device__ float  g_bqkv[QKVS];
__device__ __half g_WoT[DD*DD];
__device__ __half g_W1T[FF_*DD];
__device__ __half g_W2T[DD*FF_];

// single extern shared symbol for all kernels
extern __shared__ char smem_raw[];

// ======================= helpers =====================
__device__ __forceinline__ uint32_t smem_u32(const void* p) {
    uint32_t a;
    asm("{ .reg .u64 t; cvta.to.shared.u64 t, %1; cvt.u32.u64 %0, t; }" : "=r"(a) : "l"(p));
    return a;
}

// .cg = bypass L1, land straight in smem from L2 (stream-once data)
#define CP_ASYNC16(dst, src) \
    asm volatile("cp.async.cg.shared.global [%0], [%1], 16;" :: "r"(dst), "l"(src) : "memory")
#define CP_COMMIT()  asm volatile("cp.async.commit_group;" ::: "memory")
#define CP_WAIT1()   asm volatile("cp.async.wait_group 1;" ::: "memory")
#define CP_WAIT0()   asm volatile("cp.async.wait_group 0;" ::: "memory")

__device__ __forceinline__ void mma_f16(float c[4], uint32_t a0, uint32_t a1,
                                        uint32_t a2, uint32_t a3,
                                        uint32_t b0, uint32_t b1) {
    asm volatile(
        "mma.sync.aligned.m16n8k16.row.col.f32.f16.f16.f32 "
        "{%0,%1,%2,%3}, {%4,%5,%6,%7}, {%8,%9}, {%0,%1,%2,%3};"
        : "+f"(c[0]), "+f"(c[1]), "+f"(c[2]), "+f"(c[3])
        : "r"(a0), "r"(a1), "r"(a2), "r"(a3), "r"(b0), "r"(b1));
}
__device__ __forceinline__ void ldsm4(uint32_t r[4], uint32_t addr) {
    asm volatile("ldmatrix.sync.aligned.m8n8.x4.shared.b16 {%0,%1,%2,%3}, [%4];"
                 : "=r"(r[0]), "=r"(r[1]), "=r"(r[2]), "=r"(r[3]) : "r"(addr));
}
__device__ __forceinline__ uint32_t h2u(__half2 h) { return *(uint32_t*)&h; }

// pack two floats into half2 (lo, hi) and apply ex2 elementwise
__device__ __forceinline__ uint32_t pack_ex2_h2(float hi, float lo) {
    uint32_t d;
    asm("cvt.rn.f16x2.f32 %0, %1, %2;" : "=r"(d) : "f"(hi), "f"(lo));
    asm("ex2.approx.f16x2 %0, %0;" : "+r"(d));
    return d;
}

// ---------------- transpose kernels (fp16 out) -----------------------------
__global__ void transpose_wqkv(const float* __restrict__ Wq, const float* __restrict__ Wk,
                               const float* __restrict__ Wv, const float* __restrict__ bq,
                               const float* __restrict__ bk, const float* __restrict__ bv,
                               __half* __restrict__ WqkvT, float* __restrict__ bqkv) {
    __shared__ float t[32][33];
    int idx = blockIdx.x;
    int z = idx / 576, lo = idx % 576;
    const float* src = (z == 0) ? Wq : (z == 1) ? Wk : Wv;
    size_t dstoff = (size_t)z * DD * DD;
    int bx = lo % 24, by = lo / 24;
    int c0 = bx * 32, r0 = by * 32;
    int x = threadIdx.x, y = threadIdx.y;
    #pragma unroll
    for (int i = 0; i < 32; i += 8)
        t[y + i][x] = src[(size_t)(r0 + y + i) * DD + c0 + x];
    __syncthreads();
    #pragma unroll
    for (int i = 0; i < 32; i += 8)
        WqkvT[dstoff + (size_t)(c0 + y + i) * DD + r0 + x] = __float2half(t[x][y + i]);
    if (idx == 0) {
        int tid = y * 32 + x;
        for (int i = tid; i < QKVS; i += 256)
            bqkv[i] = (i < 768) ? bq[i] : (i < 1536) ? bk[i - 768] : bv[i - 1536];
    }
}

__global__ void transpose_wrest(const float* __restrict__ Wo, const float* __restrict__ W1,
                                const float* __restrict__ W2,
                                __half* __restrict__ WoT, __half* __restrict__ W1T,
                                __half* __restrict__ W2T) {
    __shared__ float t[32][33];
    int idx = blockIdx.x;
    const float* src; __half* dst; int R, C, bx, by;
    if (idx < 576) {
        src = Wo; dst = WoT; R = DD; C = DD; bx = idx % 24; by = idx / 24;
    } else if (idx < 2880) {
        int lo = idx - 576; src = W1; dst = W1T; R = DD; C = FF_; bx = lo % 96; by = lo / 96;
    } else {
        int lo = idx - 2880; src = W2; dst = W2T; R = FF_; C = DD; bx = lo % 24; by = lo / 24;
    }
    int c0 = bx * 32, r0 = by * 32;
    int x = threadIdx.x, y = threadIdx.y;
    #pragma unroll
    for (int i = 0; i < 32; i += 8)
        t[y + i][x] = src[(size_t)(r0 + y + i) * C + c0 + x];
    __syncthreads();
    #pragma unroll
    for (int i = 0; i < 32; i += 8)
        dst[(size_t)(c0 + y + i) * R + r0 + x] = __float2half(t[x][y + i]);
}

// ---------------- LayerNorm: warp-per-row, no block barriers ----------------
__global__ __launch_bounds__(256) void ln_kernel(
    const float* __restrict__ x, const float* __restrict__ g,
    const float* __restrict__ b, __half* __restrict__ y, float eps) {
    int w = threadIdx.x >> 5, lane = threadIdx.x & 31;
    int row = blockIdx.x * 8 + w;
    const float* xr = x + (size_t)row * DD;

    float v[24];
    float s = 0.f;
    #pragma unroll
    for (int k = 0; k < 6; k++) {
        float4 t = *(const float4*)(xr + k * 128 + lane * 4);
        v[k * 4 + 0] = t.x; v[k * 4 + 1] = t.y; v[k * 4 + 2] = t.z; v[k * 4 + 3] = t.w;
        s += t.x + t.y + t.z + t.w;
    }
    #pragma unroll
    for (int o = 16; o > 0; o >>= 1) s += __shfl_xor_sync(0xffffffffu, s, o);
    float mu = s * (1.f / DD);

    float var = 0.f;
    #pragma unroll
    for (int k = 0; k < 24; k++) { float d = v[k] - mu; var += d * d; }
    #pragma unroll
    for (int o = 16; o > 0; o >>= 1) var += __shfl_xor_sync(0xffffffffu, var, o);
    float inv = rsqrtf(var * (1.f / DD) + eps);

    __half* yr = y + (size_t)row * DD;
    #pragma unroll
    for (int k = 0; k < 6; k++) {
        int col = k * 128 + lane * 4;
        float4 gg = *(const float4*)(g + col);
        float4 bb = *(const float4*)(b + col);
        float r0 = (v[k * 4 + 0] - mu) * inv * gg.x + bb.x;
        float r1 = (v[k * 4 + 1] - mu) * inv * gg.y + bb.y;
        float r2 = (v[k * 4 + 2] - mu) * inv * gg.z + bb.z;
        float r3 = (v[k * 4 + 3] - mu) * inv * gg.w + bb.w;
        uint2 pk = { h2u(__floats2half2_rn(r0, r1)), h2u(__floats2half2_rn(r2, r3)) };
        *(uint2*)(yr + col) = pk;
    }
}

// ====== fp16 mma GEMM, 64x64 warp tiles (R15/R16 structure) ================
#define NSTAGE 3
#define GSMEM (NSTAGE * 32768)   // 96KB

template<int EPI, int HALFOUT, int VTOUT>
__global__ __launch_bounds__(128, 2) void mma_gemm(
    const __half* __restrict__ A, const __half* __restrict__ Bt,
    const float* __restrict__ bias, const float* __restrict__ res,
    void* __restrict__ Cv, __half* __restrict__ Vtp, int K, int N) {
    uint32_t smem_base = smem_u32(smem_raw);

    int tid = threadIdx.x;
    int wid = tid >> 5, lane = tid & 31;
    int r = lane >> 2, l = lane & 3;
    int quad = lane >> 3, qr = lane & 7;
    int row0 = blockIdx.y * 128, col0 = blockIdx.x * 128;
    int m0 = (wid & 1) * 64, n0 = (wid >> 1) * 64;

    int m_l = tid >> 3, s_l = tid & 7;
    const __half* srcA = A + (size_t)(row0 + m_l) * K + s_l * 8;
    const __half* srcB = Bt + (size_t)(col0 + m_l) * K + s_l * 8;
    uint32_t dA0 = smem_base + m_l * 128 + ((s_l ^ (m_l & 7)) << 4);
    uint32_t dB0 = dA0 + 16384;

    int arow = m0 + ((quad & 1) << 3) + qr;
    int xA = arow & 7, qhA = quad >> 1;
    uint32_t baseA = smem_base + arow * 128;
    int brow = n0 + ((quad >> 1) << 3) + qr;
    int xB = brow & 7, qhB = quad & 1;
    uint32_t baseB = smem_base + 16384 + brow * 128;

    int nc = K >> 6;

    float acc[4][8][4];
    #pragma unroll
    for (int i = 0; i < 4; i++)
        #pragma unroll
        for (int j = 0; j < 8; j++)
            #pragma unroll
            for (int k = 0; k < 4; k++) acc[i][j][k] = 0.f;

    #pragma unroll
    for (int s = 0; s < NSTAGE - 1; s++) {
        uint32_t so = s * 32768;
        #pragma unroll
        for (int u = 0; u < 8; u++) {
            CP_ASYNC16(dA0 + so + u * 2048, srcA + (size_t)(s * 64) + (size_t)u * 16 * K);
            CP_ASYNC16(dB0 + so + u * 2048, srcB + (size_t)(s * 64) + (size_t)u * 16 * K);
        }
        CP_COMMIT();
    }

    for (int c = 0; c < nc; c++) {
        CP_WAIT1();
        __syncthreads();
        int nstg = c + NSTAGE - 1;
        if (nstg < nc) {
            uint32_t so = (nstg % NSTAGE) * 32768;
            #pragma unroll
            for (int u = 0; u < 8; u++) {
                CP_ASYNC16(dA0 + so + u * 2048, srcA + (size_t)(nstg * 64) + (size_t)u * 16 * K);
                CP_ASYNC16(dB0 + so + u * 2048, srcB + (size_t)(nstg * 64) + (size_t)u * 16 * K);
            }
        }
        CP_COMMIT();

        uint32_t so = (c % NSTAGE) * 32768;
        #pragma unroll
        for (int ks = 0; ks < 4; ks++) {
            uint32_t segA = ((2 * ks + qhA) ^ xA) << 4;
            uint32_t segB = ((2 * ks + qhB) ^ xB) << 4;
            uint32_t a[4][4];
            #pragma unroll
            for (int mi = 0; mi < 4; mi++)
                ldsm4(a[mi], baseA + so + mi * 2048 + segA);
            #pragma unroll
            for (int p = 0; p < 4; p++) {
                uint32_t br[4];
                ldsm4(br, baseB + so + p * 2048 + segB);
                #pragma unroll
                for (int mi = 0; mi < 4; mi++) {
                    mma_f16(acc[mi][2 * p + 0], a[mi][0], a[mi][1], a[mi][2], a[mi][3], br[0], br[1]);
                    mma_f16(acc[mi][2 * p + 1], a[mi][0], a[mi][1], a[mi][2], a[mi][3], br[2], br[3]);
                }
            }
        }
    }

    bool vtile = VTOUT && (col0 >= 1536);
    #pragma unroll
    for (int mi = 0; mi < 4; mi++) {
        int rr = row0 + m0 + 16 * mi + r;
        #pragma unroll
        for (int nj = 0; nj < 8; nj++) {
            int cc = col0 + n0 + 8 * nj + 2 * l;
            float b0 = bias[cc], b1 = bias[cc + 1];
            float v0 = acc[mi][nj][0] + b0;
            float v1 = acc[mi][nj][1] + b1;
            float v2 = acc[mi][nj][2] + b0;
            float v3 = acc[mi][nj][3] + b1;
            if (EPI == 1) {
                const float* rp0 = res + (size_t)rr * N + cc;
                const float* rp1 = res + (size_t)(rr + 8) * N + cc;
                v0 += rp0[0]; v1 += rp0[1];
                v2 += rp1[0]; v3 += rp1[1];
            }
            if (EPI == 2) {
                v0 = 0.5f * v0 * (1.f + erff(v0 * 0.70710678118654752f));
                v1 = 0.5f * v1 * (1.f + erff(v1 * 0.70710678118654752f));
                v2 = 0.5f * v2 * (1.f + erff(v2 * 0.70710678118654752f));
                v3 = 0.5f * v3 * (1.f + erff(v3 * 0.70710678118654752f));
            }
            if (VTOUT) {
                if (vtile) {
                    int d = cc - 1536;
                    int hh = d >> 6, dl = d & 63;
                    int b = rr >> 10, j = rr & 1023;
                    __half* vp = Vtp + ((size_t)(b * HH + hh) * 64 + dl) * LL + j;
                    vp[0] = __float2half(v0);
                    vp[LL] = __float2half(v1);
                    vp[8] = __float2half(v2);
                    vp[LL + 8] = __float2half(v3);
                    continue;
                }
            }
            if (HALFOUT) {
                __half* Ch = (__half*)Cv;
                *(__half2*)(Ch + (size_t)rr * N + cc) = __floats2half2_rn(v0, v1);
                *(__half2*)(Ch + (size_t)(rr + 8) * N + cc) = __floats2half2_rn(v2, v3);
            } else {
                float* Cf = (float*)Cv;
                float2 o01 = { v0, v1 };
                float2 o23 = { v2, v3 };
                *(float2*)(Cf + (size_t)rr * N + cc) = o01;
                *(float2*)(Cf + (size_t)(rr + 8) * N + cc) = o23;
            }
        }
    }
}

// ======= fp16 flash attention: register P, paired 128-col K/V loads ========
#define ATB_QS 0
#define ATB_KS 16384
#define ATB_VT 32768
#define ATB_TB 49152
#define TB_RELX 0       // [2047] extended rel table, index = (j-i)+1023
#define TB_PT   2048    // [1024]
#define TB_LEX  3072    // [128]
#define TB_PIDQ 3200    // int [128]
#define TB_PIDK 3328    // int [128]
#define TB_END  3456
#define ATTN_SMEM (ATB_TB + TB_END * 4)   // 62976

__global__ __launch_bounds__(256, 2) void attn_mma(
    const __half* __restrict__ QKV, const __half* __restrict__ Vt,
    const float* __restrict__ rel_emb, const float* __restrict__ ptab,
    const int* __restrict__ pids, const float* __restrict__ lex,
    __half* __restrict__ ctx) {
    char* sb = smem_raw;
    float* tb = (float*)(sb + ATB_TB);
    int* tbi = (int*)tb;
    uint32_t sbase = smem_u32(sb);
    const float LOG2E = 1.44269504089f;

    int tid = threadIdx.x;
    int w = tid >> 5, lane = tid & 31;
    int r = lane >> 2, l = lane & 3;
    int quad = lane >> 3, qr = lane & 7;
    int h = blockIdx.y, bbx = blockIdx.z;
    int i0 = blockIdx.x * 128;

    for (int i = tid; i < 2047; i += 256) {
        int rr = min(max(i - 1023, -MAXD_), MAXD_) + MAXD_;
        tb[TB_RELX + i] = rel_emb[rr * HH + h];
    }
    for (int i = tid; i < 1024; i += 256) tb[TB_PT + i] = ptab[i * HH + h];
    if (tid < 128) tbi[TB_PIDQ + tid] = pids[bbx * LL + i0 + tid];
    {
        __half2 sc = __float2half2_rn(0.125f);
        #pragma unroll
        for (int u = 0; u < 4; u++) {
            int idx = u * 256 + tid;
            int row = idx >> 3, seg = idx & 7;
            const __half2* src = (const __half2*)(QKV + (size_t)(bbx * LL + i0 + row) * QKVS + h * 64 + seg * 8);
            __half2 v0 = __hmul2(src[0], sc), v1 = __hmul2(src[1], sc);
            __half2 v2 = __hmul2(src[2], sc), v3 = __hmul2(src[3], sc);
            uint4 pk = { h2u(v0), h2u(v1), h2u(v2), h2u(v3) };
            *(uint4*)(sb + ATB_QS + row * 128 + ((seg ^ (row & 7)) << 4)) = pk;
        }
    }
    __syncthreads();

    uint32_t aq[4][4];
    {
        int rowA = w * 16 + ((quad & 1) << 3) + qr;
        int xA = rowA & 7, qh = quad >> 1;
        uint32_t baseA = sbase + ATB_QS + rowA * 128;
        #pragma unroll
        for (int ks = 0; ks < 4; ks++)
            ldsm4(aq[ks], baseA + (((2 * ks + qh) ^ xA) << 4));
    }
    int pq0 = tbi[TB_PIDQ + w * 16 + r] * PP;
    int pq1 = tbi[TB_PIDQ + w * 16 + r + 8] * PP;

    float o[8][4];
    #pragma unroll
    for (int nj = 0; nj < 8; nj++)
        #pragma unroll
        for (int k = 0; k < 4; k++) o[nj][k] = 0.f;

    int rowK = ((quad >> 1) << 3) + qr;
    int xK = rowK & 7, qhK = quad & 1;

    float m0v = -1e30f, m1v = -1e30f, ls0 = 0.f, ls1 = 0.f;
    int rg0 = i0 + w * 16 + r, rg1 = rg0 + 8;

    for (int tp = 0; tp < 8; tp++) {
        int j0p = tp * 128;
        #pragma unroll
        for (int u = 0; u < 4; u++) {
            int idx = u * 256 + tid;
            int row = idx >> 3, seg = idx & 7;
            uint32_t sw = ((seg ^ (row & 7)) << 4);
            CP_ASYNC16(sbase + ATB_KS + row * 128 + sw,
                       QKV + (size_t)(bbx * LL + j0p + row) * QKVS + 768 + h * 64 + seg * 8);
            int d = row & 63, sub = row >> 6;
            CP_ASYNC16(sbase + ATB_VT + sub * 8192 + d * 128 + ((seg ^ (d & 7)) << 4),
                       Vt + ((size_t)(bbx * HH + h) * 64 + d) * LL + j0p + sub * 64 + seg * 8);
        }
        CP_COMMIT();
        if (tid < 128) {
            tbi[TB_PIDK + tid] = pids[bbx * LL + j0p + tid];
            tb[TB_LEX + tid] = lex[bbx * LL + j0p + tid];
        }
        CP_WAIT0();
        __syncthreads();

        #pragma unroll
        for (int sub = 0; sub < 2; sub++) {
            int j0 = j0p + sub * 64;
            uint32_t bK = sbase + ATB_KS + sub * 8192 + rowK * 128;
            uint32_t bV = sbase + ATB_VT + sub * 8192 + rowK * 128;
            const float* lexS = tb + TB_LEX + sub * 64;
            const int* pidS = tbi + TB_PIDK + sub * 64;

            float s[8][4];
            #pragma unroll
            for (int nj = 0; nj < 8; nj++)
                #pragma unroll
                for (int k = 0; k < 4; k++) s[nj][k] = 0.f;
            #pragma unroll
            for (int ks = 0; ks < 4; ks++) {
                #pragma unroll
                for (int p = 0; p < 4; p++) {
                    uint32_t br[4];
                    ldsm4(br, bK + p * 2048 + (((2 * ks + qhK) ^ xK) << 4));
                    mma_f16(s[2 * p + 0], aq[ks][0], aq[ks][1], aq[ks][2], aq[ks][3], br[0], br[1]);
                    mma_f16(s[2 * p + 1], aq[ks][0], aq[ks][1], aq[ks][2], aq[ks][3], br[2], br[3]);
                }
            }

            int off0 = j0 - rg0 + 1023 + 2 * l;
            int off1 = off0 - 8;
            float mx0 = -1e30f, mx1 = -1e30f;
            #pragma unroll
            for (int nj = 0; nj < 8; nj++) {
                int ca = nj * 8 + 2 * l;
                int2 pk2 = *(const int2*)(pidS + ca);
                float2 lx2 = *(const float2*)(lexS + ca);
                float r00 = tb[TB_RELX + off0 + nj * 8];
                float r01 = tb[TB_RELX + off0 + nj * 8 + 1];
                float r10 = tb[TB_RELX + off1 + nj * 8];
                float r11 = tb[TB_RELX + off1 + nj * 8 + 1];
                s[nj][0] += r00 + tb[TB_PT + pq0 + pk2.x] + lx2.x;
                s[nj][1] += r01 + tb[TB_PT + pq0 + pk2.y] + lx2.y;
                s[nj][2] += r10 + tb[TB_PT + pq1 + pk2.x] + lx2.x;
                s[nj][3] += r11 + tb[TB_PT + pq1 + pk2.y] + lx2.y;
                mx0 = fmaxf(mx0, fmaxf(s[nj][0], s[nj][1]));
                mx1 = fmaxf(mx1, fmaxf(s[nj][2], s[nj][3]));
            }
            mx0 = fmaxf(mx0, __shfl_xor_sync(0xffffffffu, mx0, 1));
            mx0 = fmaxf(mx0, __shfl_xor_sync(0xffffffffu, mx0, 2));
            mx1 = fmaxf(mx1, __shfl_xor_sync(0xffffffffu, mx1, 1));
            mx1 = fmaxf(mx1, __shfl_xor_sync(0xffffffffu, mx1, 2));

            float mn0 = fmaxf(m0v, mx0), mn1 = fmaxf(m1v, mx1);
            float al0 = exp2f((m0v - mn0) * LOG2E), al1 = exp2f((m1v - mn1) * LOG2E);
            m0v = mn0; m1v = mn1;

            uint32_t ph0[8], ph1[8];
            float sum0 = 0.f, sum1 = 0.f;
            #pragma unroll
            for (int nj = 0; nj < 8; nj++) {
                float t0 = (s[nj][0] - mn0) * LOG2E;
                float t1 = (s[nj][1] - mn0) * LOG2E;
                float t2 = (s[nj][2] - mn1) * LOG2E;
                float t3 = (s[nj][3] - mn1) * LOG2E;
                ph0[nj] = pack_ex2_h2(t1, t0);
                ph1[nj] = pack_ex2_h2(t3, t2);
                float2 f0 = __half22float2(*(__half2*)&ph0[nj]);
                float2 f1 = __half22float2(*(__half2*)&ph1[nj]);
                sum0 += f0.x + f0.y;
                sum1 += f1.x + f1.y;
                o[nj][0] *= al0; o[nj][1] *= al0; o[nj][2] *= al1; o[nj][3] *= al1;
            }
            sum0 += __shfl_xor_sync(0xffffffffu, sum0, 1);
            sum0 += __shfl_xor_sync(0xffffffffu, sum0, 2);
            sum1 += __shfl_xor_sync(0xffffffffu, sum1, 1);
            sum1 += __shfl_xor_sync(0xffffffffu, sum1, 2);
            ls0 = ls0 * al0 + sum0;
            ls1 = ls1 * al1 + sum1;

            #pragma unroll
            for (int kg = 0; kg < 4; kg++) {
                uint32_t a0 = ph0[2 * kg], a1 = ph1[2 * kg];
                uint32_t a2 = ph0[2 * kg + 1], a3 = ph1[2 * kg + 1];
                #pragma unroll
                for (int p = 0; p < 4; p++) {
                    uint32_t bv[4];
                    ldsm4(bv, bV + p * 2048 + (((2 * kg + qhK) ^ xK) << 4));
                    mma_f16(o[2 * p + 0], a0, a1, a2, a3, bv[0], bv[1]);
                    mma_f16(o[2 * p + 1], a0, a1, a2, a3, bv[2], bv[3]);
                }
            }
        }
        __syncthreads();
    }

    float inv0 = 1.f / ls0;
    float inv1 = 1.f / ls1;
    int row0g = bbx * LL + i0 + w * 16 + r;
    #pragma unroll
    for (int nj = 0; nj < 8; nj++) {
        *(__half2*)(ctx + (size_t)row0g * DD + h * 64 + nj * 8 + 2 * l)
            = __floats2half2_rn(o[nj][0] * inv0, o[nj][1] * inv0);
        *(__half2*)(ctx + (size_t)(row0g + 8) * DD + h * 64 + nj * 8 + 2 * l)
            = __floats2half2_rn(o[nj][2] * inv1, o[nj][3] * inv1);
    }
}

// ---------------- launch ----------------
extern "C" void kernel_launch(void* const* d_in, const int* in_sizes, int n_in,
                              void* d_out, int out_size) {
    const float* x      = (const float*)d_in[0];
    const int*   postag = (const int*)  d_in[1];
    const float* lexm   = (const float*)d_in[2];
    const float* ln1g   = (const float*)d_in[3];
    const float* ln1b   = (const float*)d_in[4];
    const float* Wq     = (const float*)d_in[5];
    const float* bq     = (const float*)d_in[6];
    const float* Wk     = (const float*)d_in[7];
    const float* bk     = (const float*)d_in[8];
    const float* Wv     = (const float*)d_in[9];
    const float* bv     = (const float*)d_in[10];
    const float* Wo     = (const float*)d_in[11];
    const float* bo     = (const float*)d_in[12];
    const float* rel    = (const float*)d_in[13];
    const float* ptab   = (const float*)d_in[14];
    const float* ln2g   = (const float*)d_in[15];
    const float* ln2b   = (const float*)d_in[16];
    const float* W1     = (const float*)d_in[17];
    const float* b1     = (const float*)d_in[18];
    const float* W2     = (const float*)d_in[19];
    const float* b2     = (const float*)d_in[20];
    float* out = (float*)d_out;

    __half *qin, *QKVb, *Vt, *ctx, *h2, *ff;
    __half *WqkvT, *WoT, *W1T, *W2T;
    float *res1, *bqkv;
    cudaGetSymbolAddress((void**)&qin,   g_qin);
    cudaGetSymbolAddress((void**)&QKVb,  g_QKV);
    cudaGetSymbolAddress((void**)&Vt,    g_Vt);
    cudaGetSymbolAddress((void**)&ctx,   g_ctx);
    cudaGetSymbolAddress((void**)&res1,  g_res1);
    cudaGetSymbolAddress((void**)&h2,    g_h2);
    cudaGetSymbolAddress((void**)&ff,    g_ff);
    cudaGetSymbolAddress((void**)&WqkvT, g_WqkvT);
    cudaGetSymbolAddress((void**)&bqkv,  g_bqkv);
    cudaGetSymbolAddress((void**)&WoT,   g_WoT);
    cudaGetSymbolAddress((void**)&W1T,   g_W1T);
    cudaGetSymbolAddress((void**)&W2T,   g_W2T);

    cudaFuncSetAttribute(attn_mma, cudaFuncAttributeMaxDynamicSharedMemorySize, ATTN_SMEM);
    cudaFuncSetAttribute(mma_gemm<0,1,1>, cudaFuncAttributeMaxDynamicSharedMemorySize, GSMEM);
    cudaFuncSetAttribute(mma_gemm<1,0,0>, cudaFuncAttributeMaxDynamicSharedMemorySize, GSMEM);
    cudaFuncSetAttribute(mma_gemm<2,1,0>, cudaFuncAttributeMaxDynamicSharedMemorySize, GSMEM);

    // 0: QKV weight transpose
    transpose_wqkv<<<1728, dim3(32, 8)>>>(Wq, Wk, Wv, bq, bk, bv, WqkvT, bqkv);
    // 1: other weight transposes
    transpose_wrest<<<5184, dim3(32, 8)>>>(Wo, W1, W2, WoT, W1T, W2T);
    // 2: LN1 -> fp16 (warp-per-row)
    ln_kernel<<<ML / 8, 256>>>(x, ln1g, ln1b, qin, 1e-6f);
    // 3: fused QKV projection (V written transposed to Vt)  <- ncu capture
    mma_gemm<0,1,1><<<dim3(QKVS / 128, ML / 128), 128, GSMEM>>>(qin, WqkvT, bqkv, nullptr, QKVb, Vt, DD, QKVS);
    // 4: attention
    attn_mma<<<dim3(LL / 128, HH, BB), 256, ATTN_SMEM>>>(QKVb, Vt, rel, ptab, postag, lexm, ctx);
    // 5: output projection + residual
    mma_gemm<1,0,0><<<dim3(DD / 128, ML / 128), 128, GSMEM>>>(ctx, WoT, bo, x, res1, nullptr, DD, DD);
    // 6: LN2 -> fp16 (warp-per-row)
    ln_kernel<<<ML / 8, 256>>>(res1, ln2g, ln2b, h2, 1e-5f);
    // 7: FFN up + GELU
    mma_gemm<2,1,0><<<dim3(FF_ / 128, ML / 128), 128, GSMEM>>>(h2, W1T, b1, nullptr, ff, nullptr, DD, FF_);
    // 8: FFN down + bias + residual -> out
    mma_gemm<1,0,0><<<dim3(DD / 128, ML / 128), 128, GSMEM>>>(ff, W2T, b2, res1, out, nullptr, FF_, DD);
}